// round 4
// baseline (speedup 1.0000x reference)
#include <cuda_runtime.h>
#include <cstdint>
#include <math.h>

#define NB  4
#define CIN 256
#define PL  128
#define HH  128
#define WW  128
#define HW  16384
#define KK  9
#define CK  1152   // PL*KK
#define LDP 136

// ---- scratch (device globals: allocation-free) ----
__device__ float g_out1_nchw[NB*PL*HW];
__device__ float g_out1_nhwc[NB*HW*PL];
__device__ float g_ident[NB*PL*HW];
__device__ float g_py[NB*KK*HW];
__device__ float g_px[NB*KK*HW];
__device__ float g_mk[NB*KK*HW];
__device__ float g_wOffT[CK*32];          // [ck][o<27, pad 32]
__device__ float g_wDcB[CK*PL];           // [K'=k*128+c][o]
__device__ float g_w3T[PL*PL];            // [c][o]
__device__ float g_w1T[CIN*PL];           // [c][o]
__device__ float g_wdsT[CIN*PL];          // [c][o]

// ---- packed f32x2 helpers ----
__device__ __forceinline__ uint64_t pack2(float lo, float hi) {
    uint64_t r; asm("mov.b64 %0, {%1, %2};" : "=l"(r) : "f"(lo), "f"(hi)); return r;
}
__device__ __forceinline__ void unpack2(uint64_t v, float& lo, float& hi) {
    asm("mov.b64 {%0, %1}, %2;" : "=f"(lo), "=f"(hi) : "l"(v));
}
__device__ __forceinline__ void ffma2(uint64_t& d, uint64_t a, uint64_t b) {
    asm("fma.rn.f32x2 %0, %1, %2, %0;" : "+l"(d) : "l"(a), "l"(b));
}

// ---------------- K0: weight transposes ----------------
__global__ void k_prep(const float* __restrict__ w_off,
                       const float* __restrict__ w_dc,
                       const float* __restrict__ w3,
                       const float* __restrict__ w1,
                       const float* __restrict__ wds) {
    int i = blockIdx.x * blockDim.x + threadIdx.x;
    if (i < CK*32) {
        int ck = i >> 5, o = i & 31;
        g_wOffT[i] = (o < 27) ? w_off[o*CK + ck] : 0.f;
    }
    if (i < CK*PL) {
        int o = i & 127, t = i >> 7;
        int c = t & 127, k = t >> 7;
        g_wDcB[i] = w_dc[(o*PL + c)*KK + k];
    }
    if (i < CIN*PL) {
        int c = i >> 7, o = i & 127;
        g_w1T[i]  = w1[o*CIN + c];
        g_wdsT[i] = wds[o*CIN + c];
    }
    if (i < PL*PL) {
        int c = i >> 7, o = i & 127;
        g_w3T[i] = w3[o*PL + c];
    }
}

// ---- shared GEMM micro-kernel: 16 k-steps, A rotated by (4k + rot0) ----
__device__ __forceinline__ void compute16(const float* __restrict__ As,
                                          const float* __restrict__ Bs,
                                          int row0, int col0, int rot0,
                                          uint64_t acc[4][8]) {
#pragma unroll
    for (int kk = 0; kk < 16; kk++) {
        int ca = (row0 + 4*kk + rot0) & 127;
        int cb = (row0 + 4 + 4*kk + rot0) & 127;
        float4 a0 = *(const float4*)&As[kk*LDP + ca];
        float4 a1 = *(const float4*)&As[kk*LDP + cb];
        float4 b0 = *(const float4*)&Bs[kk*LDP + col0];
        float4 b1 = *(const float4*)&Bs[kk*LDP + col0 + 4];
        uint64_t a2[4];
        a2[0] = pack2(a0.x, a0.y); a2[1] = pack2(a0.z, a0.w);
        a2[2] = pack2(a1.x, a1.y); a2[3] = pack2(a1.z, a1.w);
        float bj[8] = {b0.x, b0.y, b0.z, b0.w, b1.x, b1.y, b1.z, b1.w};
#pragma unroll
        for (int j = 0; j < 8; j++) {
            uint64_t b2 = pack2(bj[j], bj[j]);
#pragma unroll
            for (int i2 = 0; i2 < 4; i2++) ffma2(acc[i2][j], a2[i2], b2);
        }
    }
}

// ---------------- K1: conv1 / downsample as 128x128 f32x2 SGEMM ----------------
// grid (HW/128, 2, NB). job 0 = conv1 (out1 nchw+nhwc), job 1 = ds (ident).
__global__ __launch_bounds__(256, 2) void k_cgemm(
    const float* __restrict__ x,
    const float* __restrict__ s1a, const float* __restrict__ t1a,
    const float* __restrict__ s1b, const float* __restrict__ t1b,
    const float* __restrict__ bds, const float* __restrict__ sd, const float* __restrict__ td)
{
    __shared__ __align__(16) float Ash[2][16*LDP];
    __shared__ __align__(16) float Bsh[2][16*LDP];

    const int tid  = threadIdx.x;
    const int row0 = (tid & 15) * 8;
    const int col0 = (tid >> 4) * 8;
    const int pos0 = blockIdx.x * 128;
    const int job  = blockIdx.y;
    const int b    = blockIdx.z;
    const float* wT = job ? g_wdsT : g_w1T;
    const float* xb = x + (size_t)b * CIN * HW + pos0;

    uint64_t acc[4][8];
    const uint64_t zz = pack2(0.f, 0.f);
#pragma unroll
    for (int i2 = 0; i2 < 4; i2++)
#pragma unroll
        for (int j = 0; j < 8; j++) acc[i2][j] = zz;

    // fill chunk 0
#pragma unroll
    for (int u = 0; u < 2; u++) {
        int q = u*256 + tid, row = q >> 5, col4 = (q & 31) * 4;
        float4 av = *(const float4*)&xb[(size_t)row * HW + col4];
        Ash[0][row*LDP + ((col4 + 4*row) & 127)] = av.x;  // contiguous f4, store whole:
        *(float4*)&Ash[0][row*LDP + ((col4 + 4*row) & 127)] = av;
        float4 bv = *(const float4*)&wT[row*PL + col4];
        *(float4*)&Bsh[0][row*LDP + col4] = bv;
    }
    __syncthreads();

    for (int kc = 0; kc < 16; kc++) {
        if (kc < 15) {
            int c0 = (kc + 1) * 16;
            int nb = (kc + 1) & 1;
#pragma unroll
            for (int u = 0; u < 2; u++) {
                int q = u*256 + tid, row = q >> 5, col4 = (q & 31) * 4;
                float4 av = *(const float4*)&xb[(size_t)(c0 + row) * HW + col4];
                *(float4*)&Ash[nb][row*LDP + ((col4 + 4*row) & 127)] = av;
                float4 bv = *(const float4*)&wT[(c0 + row)*PL + col4];
                *(float4*)&Bsh[nb][row*LDP + col4] = bv;
            }
        }
        compute16(Ash[kc & 1], Bsh[kc & 1], row0, col0, 0, acc);
        __syncthreads();
    }

    if (job == 0) {
        // NCHW + bn1a/relu + bn1b/relu
#pragma unroll
        for (int j = 0; j < 8; j++) {
            int o = col0 + j;
            float sa = __ldg(s1a + o), ta = __ldg(t1a + o);
            float sb = __ldg(s1b + o), tb = __ldg(t1b + o);
            float v[8];
#pragma unroll
            for (int i2 = 0; i2 < 4; i2++) {
                float v0, v1; unpack2(acc[i2][j], v0, v1);
                v[2*i2]   = fmaxf(fmaxf(v0 * sa + ta, 0.f) * sb + tb, 0.f);
                v[2*i2+1] = fmaxf(fmaxf(v1 * sa + ta, 0.f) * sb + tb, 0.f);
            }
            size_t base = ((size_t)(b*PL + o))*HW + pos0 + row0;
            *(float4*)&g_out1_nchw[base]     = make_float4(v[0], v[1], v[2], v[3]);
            *(float4*)&g_out1_nchw[base + 4] = make_float4(v[4], v[5], v[6], v[7]);
        }
        // NHWC (recompute bn per element; trivial cost)
#pragma unroll
        for (int i2 = 0; i2 < 4; i2++) {
#pragma unroll
            for (int s = 0; s < 2; s++) {
                int p = row0 + 2*i2 + s;
                float v[8];
#pragma unroll
                for (int j = 0; j < 8; j++) {
                    int o = col0 + j;
                    float lo, hi; unpack2(acc[i2][j], lo, hi);
                    float vv = s ? hi : lo;
                    vv = fmaxf(fmaxf(vv * __ldg(s1a + o) + __ldg(t1a + o), 0.f)
                               * __ldg(s1b + o) + __ldg(t1b + o), 0.f);
                    v[j] = vv;
                }
                size_t base = ((size_t)(b*HW + pos0 + p))*PL + col0;
                *(float4*)&g_out1_nhwc[base]     = make_float4(v[0], v[1], v[2], v[3]);
                *(float4*)&g_out1_nhwc[base + 4] = make_float4(v[4], v[5], v[6], v[7]);
            }
        }
    } else {
#pragma unroll
        for (int j = 0; j < 8; j++) {
            int o = col0 + j;
            float bb = __ldg(bds + o), ss = __ldg(sd + o), tt = __ldg(td + o);
            float v[8];
#pragma unroll
            for (int i2 = 0; i2 < 4; i2++) {
                float v0, v1; unpack2(acc[i2][j], v0, v1);
                v[2*i2]   = (v0 + bb) * ss + tt;
                v[2*i2+1] = (v1 + bb) * ss + tt;
            }
            size_t base = ((size_t)(b*PL + o))*HW + pos0 + row0;
            *(float4*)&g_ident[base]     = make_float4(v[0], v[1], v[2], v[3]);
            *(float4*)&g_ident[base + 4] = make_float4(v[4], v[5], v[6], v[7]);
        }
    }
}

// ---------------- K2: offset/mask 3x3 conv (f32x2) ----------------
__global__ __launch_bounds__(128) void k_offset(const float* __restrict__ b_off) {
    const int t = threadIdx.x;
    const int lane = t & 31;
    const int h = blockIdx.x;
    const int b = blockIdx.y;
    const int xx = (t >> 5) * 32 + lane;

    uint64_t acc2[14];
    const uint64_t zz = pack2(0.f, 0.f);
#pragma unroll
    for (int i = 0; i < 14; i++) acc2[i] = zz;

    const float* inb = g_out1_nchw + (size_t)b * PL * HW;

    for (int c = 0; c < PL; c++) {
        const float* row = inb + (size_t)c * HW + h * WW;
        float sv[3][3];
#pragma unroll
        for (int dy = 0; dy < 3; dy++) {
            int yy = h + dy - 1;
            float m = 0.f, lf = 0.f, rg = 0.f;
            if (yy >= 0 && yy < HH) {
                const float* r2 = row + (dy - 1) * WW;
                m = r2[xx];
                lf = __shfl_up_sync(0xffffffffu, m, 1);
                if (lane == 0)  lf = (xx > 0) ? r2[xx - 1] : 0.f;
                rg = __shfl_down_sync(0xffffffffu, m, 1);
                if (lane == 31) rg = (xx < WW - 1) ? r2[xx + 1] : 0.f;
            }
            sv[dy][0] = lf; sv[dy][1] = m; sv[dy][2] = rg;
        }
#pragma unroll
        for (int k = 0; k < 9; k++) {
            float s = sv[k/3][k%3];
            uint64_t s2 = pack2(s, s);
            const ulonglong2* wp = (const ulonglong2*)&g_wOffT[(c*9 + k) * 32];
#pragma unroll
            for (int j = 0; j < 7; j++) {
                ulonglong2 w2 = wp[j];
                ffma2(acc2[2*j],     w2.x, s2);
                ffma2(acc2[2*j + 1], w2.y, s2);
            }
        }
    }

    float acc[28];
#pragma unroll
    for (int j = 0; j < 14; j++) unpack2(acc2[j], acc[2*j], acc[2*j + 1]);

    const int pos = h * WW + xx;
#pragma unroll
    for (int k = 0; k < 9; k++) {
        float dyv = acc[k]      + b_off[k];
        float dxv = acc[9 + k]  + b_off[9 + k];
        float z   = acc[18 + k] + b_off[18 + k];
        float mk  = 1.f / (1.f + expf(-z));
        int idx = (b*KK + k)*HW + pos;
        g_py[idx] = (float)(h - 1 + k/3) + dyv;
        g_px[idx] = (float)(xx - 1 + k%3) + dxv;
        g_mk[idx] = mk;
    }
}

// ---------------- K3: deform GEMM + bn2/relu + conv3 + bn3s + residual ----------------
// SMEM floats: A[2][32][136] @0 (8704), B[2][32][136] @8704, coords @17408 (3x1152)
//              V [128][136] @0 (17408) ; B2 [16][136] @17408  (reuse after mainloop)
#define SMF_A   0
#define SMF_B   8704
#define SMF_CY  17408
#define SMF_CX  (SMF_CY + 1152)
#define SMF_CM  (SMF_CX + 1152)
#define SMF_V   0
#define SMF_B2  17408
#define SMEM_TOT (20864 * 4)

__global__ __launch_bounds__(256, 2) void k_dgemm(
    const float* __restrict__ b_dc, const float* __restrict__ s2, const float* __restrict__ t2,
    const float* __restrict__ s3a, const float* __restrict__ t3a,
    const float* __restrict__ s3b, const float* __restrict__ t3b,
    float* __restrict__ out)
{
    extern __shared__ __align__(16) float smf[];
    float* cY = smf + SMF_CY;
    float* cX = smf + SMF_CX;
    float* cM = smf + SMF_CM;

    const int tid  = threadIdx.x;
    const int lane = tid & 31;
    const int w    = tid >> 5;
    const int row0 = (tid & 15) * 8;
    const int col0 = (tid >> 4) * 8;
    const int pos0 = blockIdx.x * 128;
    const int b    = pos0 >> 14;
    const int pim0 = pos0 & (HW - 1);

    for (int idx = tid; idx < 1152; idx += 256) {
        int k = idx >> 7, p = idx & 127;
        int gidx = (b*KK + k)*HW + pim0 + p;
        cY[idx] = g_py[gidx]; cX[idx] = g_px[gidx]; cM[idx] = g_mk[gidx];
    }
    __syncthreads();

    const float* nhwc = g_out1_nhwc + (size_t)b * HW * PL;

    uint64_t acc[4][8];
    const uint64_t zz = pack2(0.f, 0.f);
#pragma unroll
    for (int i2 = 0; i2 < 4; i2++)
#pragma unroll
        for (int j = 0; j < 8; j++) acc[i2][j] = zz;

    // fill(chunk kc, buffer bf): channel-major gather + weight tile
    auto fill = [&](int kc, int bf) {
        const int tap = kc >> 2;
        const int c0  = (kc & 3) << 5;
        float* Ab = smf + SMF_A + bf * 32*LDP;
        float* Bb = smf + SMF_B + bf * 32*LDP;
        const float* cyk = cY + tap*128;
        const float* cxk = cX + tap*128;
        const float* cmk = cM + tap*128;
#pragma unroll 4
        for (int i = 0; i < 16; i++) {
            int p = w*16 + i;
            float py = cyk[p], px = cxk[p], mk = cmk[p];
            float fy = floorf(py), fx = floorf(px);
            float wy = py - fy, wx = px - fx;
            int y0 = (int)fy, x0 = (int)fx;
            bool y0k = ((unsigned)y0 < HH), y1k = ((unsigned)(y0+1) < HH);
            bool x0k = ((unsigned)x0 < WW), x1k = ((unsigned)(x0+1) < WW);
            float w00 = (1.f-wy)*(1.f-wx)*mk, w01 = (1.f-wy)*wx*mk;
            float w10 = wy*(1.f-wx)*mk,       w11 = wy*wx*mk;
            const float* p00 = nhwc + ((long)y0*WW + x0)*PL + c0 + lane;
            float v00 = 0.f, v01 = 0.f, v10 = 0.f, v11 = 0.f;
            if (y0k && x0k) v00 = p00[0];
            if (y0k && x1k) v01 = p00[PL];
            if (y1k && x0k) v10 = p00[WW*PL];
            if (y1k && x1k) v11 = p00[WW*PL + PL];
            float val = v00*w00 + v01*w01 + v10*w10 + v11*w11;
            Ab[lane*LDP + ((p + 4*lane) & 127)] = val;
        }
#pragma unroll
        for (int u = 0; u < 4; u++) {
            int q = u*256 + tid, rr = q >> 5, col4 = (q & 31) * 4;
            float4 bv = *(const float4*)&g_wDcB[((size_t)kc*32 + rr)*PL + col4];
            *(float4*)&Bb[rr*LDP + col4] = bv;
        }
    };

    fill(0, 0);
    __syncthreads();

    for (int kc = 0; kc < 36; kc++) {
        if (kc < 35) fill(kc + 1, (kc + 1) & 1);
        const float* Ab = smf + SMF_A + (kc & 1) * 32*LDP;
        const float* Bb = smf + SMF_B + (kc & 1) * 32*LDP;
        compute16(Ab, Bb, row0, col0, 0, acc);
        compute16(Ab + 16*LDP, Bb + 16*LDP, row0, col0, 64, acc);
        __syncthreads();
    }

    // epilogue 1: v = relu(bn2(acc + b_dc)) -> V[c][rot(pos)]
    float* Vs = smf + SMF_V;
#pragma unroll
    for (int j = 0; j < 8; j++) {
        int c = col0 + j;
        float bb = __ldg(b_dc + c), ss = __ldg(s2 + c), tt = __ldg(t2 + c);
#pragma unroll
        for (int i2 = 0; i2 < 4; i2++) {
            float v0, v1; unpack2(acc[i2][j], v0, v1);
            v0 = fmaxf((v0 + bb) * ss + tt, 0.f);
            v1 = fmaxf((v1 + bb) * ss + tt, 0.f);
            *(float2*)&Vs[c*LDP + ((row0 + 2*i2 + 4*c) & 127)] = make_float2(v0, v1);
        }
    }

    // GEMM2: conv3 over K=128 in 8 chunks of 16
    uint64_t acc3[4][8];
#pragma unroll
    for (int i2 = 0; i2 < 4; i2++)
#pragma unroll
        for (int j = 0; j < 8; j++) acc3[i2][j] = zz;

    float* B2 = smf + SMF_B2;
    for (int cb = 0; cb < 8; cb++) {
        float4 r[2];
#pragma unroll
        for (int u = 0; u < 2; u++) {
            int q = u*256 + tid, rr = q >> 5, col4 = (q & 31) * 4;
            r[u] = *(const float4*)&g_w3T[((size_t)cb*16 + rr)*PL + col4];
        }
        __syncthreads();
#pragma unroll
        for (int u = 0; u < 2; u++) {
            int q = u*256 + tid, rr = q >> 5, col4 = (q & 31) * 4;
            *(float4*)&B2[rr*LDP + col4] = r[u];
        }
        __syncthreads();
        compute16(Vs + cb*16*LDP, B2, row0, col0, (64*cb) & 127, acc3);
    }

    // epilogue 2: bn3a/relu/bn3b + identity + relu -> NCHW float4 stores
#pragma unroll
    for (int j = 0; j < 8; j++) {
        int c = col0 + j;
        float sa = __ldg(s3a + c), ta = __ldg(t3a + c);
        float sb = __ldg(s3b + c), tb = __ldg(t3b + c);
        float v[8];
#pragma unroll
        for (int i2 = 0; i2 < 4; i2++) {
            float v0, v1; unpack2(acc3[i2][j], v0, v1);
            v[2*i2]     = fmaxf(v0 * sa + ta, 0.f) * sb + tb;
            v[2*i2 + 1] = fmaxf(v1 * sa + ta, 0.f) * sb + tb;
        }
        size_t base = ((size_t)(b*PL + c))*HW + pim0 + row0;
        float4 id0 = *(const float4*)&g_ident[base];
        float4 id1 = *(const float4*)&g_ident[base + 4];
        *(float4*)&out[base] = make_float4(
            fmaxf(v[0] + id0.x, 0.f), fmaxf(v[1] + id0.y, 0.f),
            fmaxf(v[2] + id0.z, 0.f), fmaxf(v[3] + id0.w, 0.f));
        *(float4*)&out[base + 4] = make_float4(
            fmaxf(v[4] + id1.x, 0.f), fmaxf(v[5] + id1.y, 0.f),
            fmaxf(v[6] + id1.z, 0.f), fmaxf(v[7] + id1.w, 0.f));
    }
}

// ---------------- host ----------------
extern "C" void kernel_launch(void* const* d_in, const int* in_sizes, int n_in,
                              void* d_out, int out_size) {
    const float* x    = (const float*)d_in[0];
    const float* w1   = (const float*)d_in[1];
    const float* s1a  = (const float*)d_in[2];
    const float* t1a  = (const float*)d_in[3];
    const float* s1b  = (const float*)d_in[4];
    const float* t1b  = (const float*)d_in[5];
    const float* w_off= (const float*)d_in[6];
    const float* b_off= (const float*)d_in[7];
    const float* w_dc = (const float*)d_in[8];
    const float* b_dc = (const float*)d_in[9];
    const float* s2   = (const float*)d_in[10];
    const float* t2   = (const float*)d_in[11];
    const float* w3   = (const float*)d_in[12];
    const float* s3a  = (const float*)d_in[13];
    const float* t3a  = (const float*)d_in[14];
    const float* s3b  = (const float*)d_in[15];
    const float* t3b  = (const float*)d_in[16];
    const float* w_ds = (const float*)d_in[17];
    const float* b_ds = (const float*)d_in[18];
    const float* sd   = (const float*)d_in[19];
    const float* td   = (const float*)d_in[20];
    float* out = (float*)d_out;

    k_prep<<<(CK*PL + 255)/256, 256>>>(w_off, w_dc, w3, w1, w_ds);

    dim3 g1(HW/128, 2, NB);
    k_cgemm<<<g1, 256>>>(x, s1a, t1a, s1b, t1b, b_ds, sd, td);

    dim3 g2(HH, NB);
    k_offset<<<g2, 128>>>(b_off);

    cudaFuncSetAttribute(k_dgemm, cudaFuncAttributeMaxDynamicSharedMemorySize, SMEM_TOT);
    k_dgemm<<<NB*HW/128, 256, SMEM_TOT>>>(b_dc, s2, t2, s3a, t3a, s3b, t3b, out);
}

// round 5
// speedup vs baseline: 1.3413x; 1.3413x over previous
#include <cuda_runtime.h>
#include <cstdint>
#include <math.h>

#define NB  4
#define CIN 256
#define PL  128
#define HH  128
#define WW  128
#define HW  16384
#define KK  9
#define CK  1152   // PL*KK
#define LDP 136

// ---- scratch (device globals: allocation-free) ----
__device__ float g_out1_nchw[NB*PL*HW];
__device__ float g_out1_nhwc[NB*HW*PL];
__device__ float g_ident[NB*PL*HW];
__device__ float g_py[NB*KK*HW];
__device__ float g_px[NB*KK*HW];
__device__ float g_mk[NB*KK*HW];
__device__ float g_wOffT[CK*32];          // [ck][o<27, pad 32]  (f32)
__device__ float g_wDcB[CK*PL];           // [K'=k*128+c][o]     (tf32 bits)
__device__ float g_w3T[PL*PL];            // [c][o]              (tf32 bits)
__device__ float g_w1T[CIN*PL];           // [c][o]              (f32)
__device__ float g_wdsT[CIN*PL];          // [c][o]              (f32)

// ---- packed f32x2 helpers (for k_cgemm / k_offset) ----
__device__ __forceinline__ uint64_t pack2(float lo, float hi) {
    uint64_t r; asm("mov.b64 %0, {%1, %2};" : "=l"(r) : "f"(lo), "f"(hi)); return r;
}
__device__ __forceinline__ void unpack2(uint64_t v, float& lo, float& hi) {
    asm("mov.b64 {%0, %1}, %2;" : "=f"(lo), "=f"(hi) : "l"(v));
}
__device__ __forceinline__ void ffma2(uint64_t& d, uint64_t a, uint64_t b) {
    asm("fma.rn.f32x2 %0, %1, %2, %0;" : "+l"(d) : "l"(a), "l"(b));
}

// ---- tf32 mma helpers ----
__device__ __forceinline__ uint32_t f2tf(float x) {
    uint32_t r; asm("cvt.rna.tf32.f32 %0, %1;" : "=r"(r) : "f"(x)); return r;
}
__device__ __forceinline__ void mma_tf32(float d[4], const uint32_t a[4], const uint32_t b[2]) {
    asm volatile("mma.sync.aligned.m16n8k8.row.col.f32.tf32.tf32.f32 "
        "{%0,%1,%2,%3}, {%4,%5,%6,%7}, {%8,%9}, {%0,%1,%2,%3};"
        : "+f"(d[0]), "+f"(d[1]), "+f"(d[2]), "+f"(d[3])
        : "r"(a[0]), "r"(a[1]), "r"(a[2]), "r"(a[3]), "r"(b[0]), "r"(b[1]));
}

// ---------------- K0: weight transposes (+tf32 conversion for mma weights) ----------------
__global__ void k_prep(const float* __restrict__ w_off,
                       const float* __restrict__ w_dc,
                       const float* __restrict__ w3,
                       const float* __restrict__ w1,
                       const float* __restrict__ wds) {
    int i = blockIdx.x * blockDim.x + threadIdx.x;
    if (i < CK*32) {
        int ck = i >> 5, o = i & 31;
        g_wOffT[i] = (o < 27) ? w_off[o*CK + ck] : 0.f;
    }
    if (i < CK*PL) {
        int o = i & 127, t = i >> 7;
        int c = t & 127, k = t >> 7;
        g_wDcB[i] = __uint_as_float(f2tf(w_dc[(o*PL + c)*KK + k]));
    }
    if (i < CIN*PL) {
        int c = i >> 7, o = i & 127;
        g_w1T[i]  = w1[o*CIN + c];
        g_wdsT[i] = wds[o*CIN + c];
    }
    if (i < PL*PL) {
        int c = i >> 7, o = i & 127;
        g_w3T[i] = __uint_as_float(f2tf(w3[o*PL + c]));
    }
}

// ---- f32x2 GEMM micro-kernel (k_cgemm only) ----
__device__ __forceinline__ void compute16(const float* __restrict__ As,
                                          const float* __restrict__ Bs,
                                          int row0, int col0, uint64_t acc[4][8]) {
#pragma unroll
    for (int kk = 0; kk < 16; kk++) {
        float4 a0 = *(const float4*)&As[kk*LDP + row0];
        float4 a1 = *(const float4*)&As[kk*LDP + row0 + 4];
        float4 b0 = *(const float4*)&Bs[kk*LDP + col0];
        float4 b1 = *(const float4*)&Bs[kk*LDP + col0 + 4];
        uint64_t a2[4];
        a2[0] = pack2(a0.x, a0.y); a2[1] = pack2(a0.z, a0.w);
        a2[2] = pack2(a1.x, a1.y); a2[3] = pack2(a1.z, a1.w);
        float bj[8] = {b0.x, b0.y, b0.z, b0.w, b1.x, b1.y, b1.z, b1.w};
#pragma unroll
        for (int j = 0; j < 8; j++) {
            uint64_t b2 = pack2(bj[j], bj[j]);
#pragma unroll
            for (int i2 = 0; i2 < 4; i2++) ffma2(acc[i2][j], a2[i2], b2);
        }
    }
}

// ---------------- K1: conv1 / downsample as 128x128 f32x2 SGEMM ----------------
__global__ __launch_bounds__(256, 2) void k_cgemm(
    const float* __restrict__ x,
    const float* __restrict__ s1a, const float* __restrict__ t1a,
    const float* __restrict__ s1b, const float* __restrict__ t1b,
    const float* __restrict__ bds, const float* __restrict__ sd, const float* __restrict__ td)
{
    __shared__ __align__(16) float Ash[2][16*LDP];
    __shared__ __align__(16) float Bsh[2][16*LDP];

    const int tid  = threadIdx.x;
    const int row0 = (tid & 15) * 8;
    const int col0 = (tid >> 4) * 8;
    const int pos0 = blockIdx.x * 128;
    const int job  = blockIdx.y;
    const int b    = blockIdx.z;
    const float* wT = job ? g_wdsT : g_w1T;
    const float* xb = x + (size_t)b * CIN * HW + pos0;

    uint64_t acc[4][8];
    const uint64_t zz = pack2(0.f, 0.f);
#pragma unroll
    for (int i2 = 0; i2 < 4; i2++)
#pragma unroll
        for (int j = 0; j < 8; j++) acc[i2][j] = zz;

#pragma unroll
    for (int u = 0; u < 2; u++) {
        int q = u*256 + tid, row = q >> 5, col4 = (q & 31) * 4;
        *(float4*)&Ash[0][row*LDP + col4] = *(const float4*)&xb[(size_t)row * HW + col4];
        *(float4*)&Bsh[0][row*LDP + col4] = *(const float4*)&wT[row*PL + col4];
    }
    __syncthreads();

    for (int kc = 0; kc < 16; kc++) {
        if (kc < 15) {
            int c0 = (kc + 1) * 16;
            int nb = (kc + 1) & 1;
#pragma unroll
            for (int u = 0; u < 2; u++) {
                int q = u*256 + tid, row = q >> 5, col4 = (q & 31) * 4;
                *(float4*)&Ash[nb][row*LDP + col4] = *(const float4*)&xb[(size_t)(c0 + row) * HW + col4];
                *(float4*)&Bsh[nb][row*LDP + col4] = *(const float4*)&wT[(c0 + row)*PL + col4];
            }
        }
        compute16(Ash[kc & 1], Bsh[kc & 1], row0, col0, acc);
        __syncthreads();
    }

    if (job == 0) {
#pragma unroll
        for (int j = 0; j < 8; j++) {
            int o = col0 + j;
            float sa = __ldg(s1a + o), ta = __ldg(t1a + o);
            float sb = __ldg(s1b + o), tb = __ldg(t1b + o);
            float v[8];
#pragma unroll
            for (int i2 = 0; i2 < 4; i2++) {
                float v0, v1; unpack2(acc[i2][j], v0, v1);
                v[2*i2]   = fmaxf(fmaxf(v0 * sa + ta, 0.f) * sb + tb, 0.f);
                v[2*i2+1] = fmaxf(fmaxf(v1 * sa + ta, 0.f) * sb + tb, 0.f);
            }
            size_t base = ((size_t)(b*PL + o))*HW + pos0 + row0;
            *(float4*)&g_out1_nchw[base]     = make_float4(v[0], v[1], v[2], v[3]);
            *(float4*)&g_out1_nchw[base + 4] = make_float4(v[4], v[5], v[6], v[7]);
        }
#pragma unroll
        for (int i2 = 0; i2 < 4; i2++) {
#pragma unroll
            for (int s = 0; s < 2; s++) {
                int p = row0 + 2*i2 + s;
                float v[8];
#pragma unroll
                for (int j = 0; j < 8; j++) {
                    int o = col0 + j;
                    float lo, hi; unpack2(acc[i2][j], lo, hi);
                    float vv = s ? hi : lo;
                    vv = fmaxf(fmaxf(vv * __ldg(s1a + o) + __ldg(t1a + o), 0.f)
                               * __ldg(s1b + o) + __ldg(t1b + o), 0.f);
                    v[j] = vv;
                }
                size_t base = ((size_t)(b*HW + pos0 + p))*PL + col0;
                *(float4*)&g_out1_nhwc[base]     = make_float4(v[0], v[1], v[2], v[3]);
                *(float4*)&g_out1_nhwc[base + 4] = make_float4(v[4], v[5], v[6], v[7]);
            }
        }
    } else {
#pragma unroll
        for (int j = 0; j < 8; j++) {
            int o = col0 + j;
            float bb = __ldg(bds + o), ss = __ldg(sd + o), tt = __ldg(td + o);
            float v[8];
#pragma unroll
            for (int i2 = 0; i2 < 4; i2++) {
                float v0, v1; unpack2(acc[i2][j], v0, v1);
                v[2*i2]   = (v0 + bb) * ss + tt;
                v[2*i2+1] = (v1 + bb) * ss + tt;
            }
            size_t base = ((size_t)(b*PL + o))*HW + pos0 + row0;
            *(float4*)&g_ident[base]     = make_float4(v[0], v[1], v[2], v[3]);
            *(float4*)&g_ident[base + 4] = make_float4(v[4], v[5], v[6], v[7]);
        }
    }
}

// ---------------- K2: offset/mask 3x3 conv (f32x2) ----------------
__global__ __launch_bounds__(128) void k_offset(const float* __restrict__ b_off) {
    const int t = threadIdx.x;
    const int lane = t & 31;
    const int h = blockIdx.x;
    const int b = blockIdx.y;
    const int xx = (t >> 5) * 32 + lane;

    uint64_t acc2[14];
    const uint64_t zz = pack2(0.f, 0.f);
#pragma unroll
    for (int i = 0; i < 14; i++) acc2[i] = zz;

    const float* inb = g_out1_nchw + (size_t)b * PL * HW;

    for (int c = 0; c < PL; c++) {
        const float* row = inb + (size_t)c * HW + h * WW;
        float sv[3][3];
#pragma unroll
        for (int dy = 0; dy < 3; dy++) {
            int yy = h + dy - 1;
            float m = 0.f, lf = 0.f, rg = 0.f;
            if (yy >= 0 && yy < HH) {
                const float* r2 = row + (dy - 1) * WW;
                m = r2[xx];
                lf = __shfl_up_sync(0xffffffffu, m, 1);
                if (lane == 0)  lf = (xx > 0) ? r2[xx - 1] : 0.f;
                rg = __shfl_down_sync(0xffffffffu, m, 1);
                if (lane == 31) rg = (xx < WW - 1) ? r2[xx + 1] : 0.f;
            }
            sv[dy][0] = lf; sv[dy][1] = m; sv[dy][2] = rg;
        }
#pragma unroll
        for (int k = 0; k < 9; k++) {
            float s = sv[k/3][k%3];
            uint64_t s2 = pack2(s, s);
            const ulonglong2* wp = (const ulonglong2*)&g_wOffT[(c*9 + k) * 32];
#pragma unroll
            for (int j = 0; j < 7; j++) {
                ulonglong2 w2 = wp[j];
                ffma2(acc2[2*j],     w2.x, s2);
                ffma2(acc2[2*j + 1], w2.y, s2);
            }
        }
    }

    float acc[28];
#pragma unroll
    for (int j = 0; j < 14; j++) unpack2(acc2[j], acc[2*j], acc[2*j + 1]);

    const int pos = h * WW + xx;
#pragma unroll
    for (int k = 0; k < 9; k++) {
        float dyv = acc[k]      + b_off[k];
        float dxv = acc[9 + k]  + b_off[9 + k];
        float z   = acc[18 + k] + b_off[18 + k];
        float mk  = 1.f / (1.f + expf(-z));
        int idx = (b*KK + k)*HW + pos;
        g_py[idx] = (float)(h - 1 + k/3) + dyv;
        g_px[idx] = (float)(xx - 1 + k%3) + dxv;
        g_mk[idx] = mk;
    }
}

// ---------------- K3: deform GEMM via tf32 mma.sync + conv3 + residual ----------------
// SMEM floats: A[2][16][136] @0, B[2][16][136] @4352, coords @8704 (3x1152 -> end 12160)
//              V/F [128][136] @0 (17408) ; B2 [16][136] @17408   SMEM_TOT = 19584 floats
#define SMF_A   0
#define SMF_B   4352
#define SMF_CY  8704
#define SMF_CX  (SMF_CY + 1152)
#define SMF_CM  (SMF_CX + 1152)
#define SMF_V   0
#define SMF_B2  17408
#define SMEM_TOT (19584 * 4)

__device__ __forceinline__ void gather8(const float* __restrict__ nhwc,
                                        const float* cY, const float* cX, const float* cM,
                                        int tap, int pos, int cbase, float st[8]) {
    int ci = tap*128 + pos;
    float py = cY[ci], px = cX[ci], mk = cM[ci];
    float fy = floorf(py), fx = floorf(px);
    float wy = py - fy, wx = px - fx;
    int y0 = (int)fy, x0 = (int)fx;
    bool y0k = ((unsigned)y0 < HH), y1k = ((unsigned)(y0+1) < HH);
    bool x0k = ((unsigned)x0 < WW), x1k = ((unsigned)(x0+1) < WW);
    float w00 = (1.f-wy)*(1.f-wx)*mk, w01 = (1.f-wy)*wx*mk;
    float w10 = wy*(1.f-wx)*mk,       w11 = wy*wx*mk;
    const float* p00 = nhwc + ((long)y0*WW + x0)*PL + cbase;
    float4 z = make_float4(0.f, 0.f, 0.f, 0.f);
    bool v00 = y0k && x0k, v01 = y0k && x1k, v10 = y1k && x0k, v11 = y1k && x1k;
    float4 q00a = v00 ? *(const float4*)p00 : z;
    float4 q00b = v00 ? *(const float4*)(p00 + 4) : z;
    float4 q01a = v01 ? *(const float4*)(p00 + PL) : z;
    float4 q01b = v01 ? *(const float4*)(p00 + PL + 4) : z;
    float4 q10a = v10 ? *(const float4*)(p00 + WW*PL) : z;
    float4 q10b = v10 ? *(const float4*)(p00 + WW*PL + 4) : z;
    float4 q11a = v11 ? *(const float4*)(p00 + WW*PL + PL) : z;
    float4 q11b = v11 ? *(const float4*)(p00 + WW*PL + PL + 4) : z;
    st[0] = q00a.x*w00 + q01a.x*w01 + q10a.x*w10 + q11a.x*w11;
    st[1] = q00a.y*w00 + q01a.y*w01 + q10a.y*w10 + q11a.y*w11;
    st[2] = q00a.z*w00 + q01a.z*w01 + q10a.z*w10 + q11a.z*w11;
    st[3] = q00a.w*w00 + q01a.w*w01 + q10a.w*w10 + q11a.w*w11;
    st[4] = q00b.x*w00 + q01b.x*w01 + q10b.x*w10 + q11b.x*w11;
    st[5] = q00b.y*w00 + q01b.y*w01 + q10b.y*w10 + q11b.y*w11;
    st[6] = q00b.z*w00 + q01b.z*w01 + q10b.z*w10 + q11b.z*w11;
    st[7] = q00b.w*w00 + q01b.w*w01 + q10b.w*w10 + q11b.w*w11;
}

__global__ __launch_bounds__(256, 2) void k_dgemm(
    const float* __restrict__ b_dc, const float* __restrict__ s2, const float* __restrict__ t2,
    const float* __restrict__ s3a, const float* __restrict__ t3a,
    const float* __restrict__ s3b, const float* __restrict__ t3b,
    float* __restrict__ out)
{
    extern __shared__ __align__(16) float smf[];
    float* cY = smf + SMF_CY;
    float* cX = smf + SMF_CX;
    float* cM = smf + SMF_CM;

    const int tid  = threadIdx.x;
    const int wrp  = tid >> 5;
    const int t3   = tid & 3;            // thread-in-group (quad id)
    const int g    = (tid & 31) >> 2;    // group id 0..7
    const int m0   = (wrp & 3) * 32;     // warp M offset
    const int n0   = (wrp >> 2) * 64;    // warp N offset
    const int gpos = tid >> 1;           // gather position
    const int cg   = (tid & 1) * 8;      // gather channel sub-offset
    const int bkk  = (tid*2) >> 5;       // B-tile row
    const int bo4  = ((tid*2) & 31) * 4; // B-tile col
    const int pos0 = blockIdx.x * 128;
    const int b    = pos0 >> 14;
    const int pim0 = pos0 & (HW - 1);

    for (int idx = tid; idx < 1152; idx += 256) {
        int k = idx >> 7, p = idx & 127;
        int gidx = (b*KK + k)*HW + pim0 + p;
        cY[idx] = g_py[gidx]; cX[idx] = g_px[gidx]; cM[idx] = g_mk[gidx];
    }
    __syncthreads();

    const float* nhwc = g_out1_nhwc + (size_t)b * HW * PL;

    float acc[2][8][4];
#pragma unroll
    for (int mt = 0; mt < 2; mt++)
#pragma unroll
        for (int nt = 0; nt < 8; nt++)
#pragma unroll
            for (int i = 0; i < 4; i++) acc[mt][nt][i] = 0.f;

    auto fill = [&](int kc, int bf) {
        float st[8];
        gather8(nhwc, cY, cX, cM, kc >> 3, gpos, ((kc & 7) << 4) + cg, st);
        float* Ab = smf + SMF_A + bf * 2176;
        float* Bb = smf + SMF_B + bf * 2176;
#pragma unroll
        for (int j = 0; j < 8; j++)
            Ab[(cg + j)*LDP + gpos] = __uint_as_float(f2tf(st[j]));
        const float* src = g_wDcB + ((size_t)kc*16 + bkk)*PL + bo4;
        *(float4*)&Bb[bkk*LDP + bo4]     = *(const float4*)src;
        *(float4*)&Bb[bkk*LDP + bo4 + 4] = *(const float4*)(src + 4);
    };

    fill(0, 0);
    __syncthreads();

    for (int kc = 0; kc < 72; kc++) {
        if (kc < 71) fill(kc + 1, (kc + 1) & 1);
        const uint32_t* As = (const uint32_t*)(smf + SMF_A + (kc & 1) * 2176);
        const uint32_t* Bs = (const uint32_t*)(smf + SMF_B + (kc & 1) * 2176);
#pragma unroll
        for (int ks = 0; ks < 16; ks += 8) {
            uint32_t a[2][4];
#pragma unroll
            for (int mt = 0; mt < 2; mt++) {
                int rb = m0 + mt*16 + g;
                a[mt][0] = As[(ks + t3)*LDP + rb];
                a[mt][1] = As[(ks + t3)*LDP + rb + 8];
                a[mt][2] = As[(ks + t3 + 4)*LDP + rb];
                a[mt][3] = As[(ks + t3 + 4)*LDP + rb + 8];
            }
#pragma unroll
            for (int nt = 0; nt < 8; nt++) {
                uint32_t bb[2];
                bb[0] = Bs[(ks + t3)*LDP + n0 + nt*8 + g];
                bb[1] = Bs[(ks + t3 + 4)*LDP + n0 + nt*8 + g];
                mma_tf32(acc[0][nt], a[0], bb);
                mma_tf32(acc[1][nt], a[1], bb);
            }
        }
        __syncthreads();
    }

    // epilogue 1: v = relu(bn2(acc + b_dc)) -> Vs[c][pos] (tf32 bits)
    float* Vs = smf + SMF_V;
#pragma unroll
    for (int nt = 0; nt < 8; nt++) {
        int c0 = n0 + nt*8 + 2*t3;
        float b0 = __ldg(b_dc + c0),     ss0 = __ldg(s2 + c0),     tt0 = __ldg(t2 + c0);
        float b1 = __ldg(b_dc + c0 + 1), ss1 = __ldg(s2 + c0 + 1), tt1 = __ldg(t2 + c0 + 1);
#pragma unroll
        for (int mt = 0; mt < 2; mt++) {
            int plo = m0 + mt*16 + g;
            float v0 = fmaxf((acc[mt][nt][0] + b0) * ss0 + tt0, 0.f);
            float v1 = fmaxf((acc[mt][nt][1] + b1) * ss1 + tt1, 0.f);
            float v2 = fmaxf((acc[mt][nt][2] + b0) * ss0 + tt0, 0.f);
            float v3 = fmaxf((acc[mt][nt][3] + b1) * ss1 + tt1, 0.f);
            Vs[c0*LDP + plo]           = __uint_as_float(f2tf(v0));
            Vs[(c0 + 1)*LDP + plo]     = __uint_as_float(f2tf(v1));
            Vs[c0*LDP + plo + 8]       = __uint_as_float(f2tf(v2));
            Vs[(c0 + 1)*LDP + plo + 8] = __uint_as_float(f2tf(v3));
        }
    }
    __syncthreads();

    // GEMM2: conv3, K=128 in 8 chunks of 16 (A = Vs, B = g_w3T chunk)
    float acc3[2][8][4];
#pragma unroll
    for (int mt = 0; mt < 2; mt++)
#pragma unroll
        for (int nt = 0; nt < 8; nt++)
#pragma unroll
            for (int i = 0; i < 4; i++) acc3[mt][nt][i] = 0.f;

    float* B2 = smf + SMF_B2;
    for (int cb = 0; cb < 8; cb++) {
        float4 r[2];
#pragma unroll
        for (int u = 0; u < 2; u++) {
            int q = u*256 + tid, rr = q >> 5, col4 = (q & 31) * 4;
            r[u] = *(const float4*)&g_w3T[((size_t)cb*16 + rr)*PL + col4];
        }
        __syncthreads();
#pragma unroll
        for (int u = 0; u < 2; u++) {
            int q = u*256 + tid, rr = q >> 5, col4 = (q & 31) * 4;
            *(float4*)&B2[rr*LDP + col4] = r[u];
        }
        __syncthreads();
        const uint32_t* As = (const uint32_t*)Vs;
        const uint32_t* Bs = (const uint32_t*)B2;
#pragma unroll
        for (int ks = 0; ks < 16; ks += 8) {
            uint32_t a[2][4];
#pragma unroll
            for (int mt = 0; mt < 2; mt++) {
                int rb = m0 + mt*16 + g;
                a[mt][0] = As[(cb*16 + ks + t3)*LDP + rb];
                a[mt][1] = As[(cb*16 + ks + t3)*LDP + rb + 8];
                a[mt][2] = As[(cb*16 + ks + t3 + 4)*LDP + rb];
                a[mt][3] = As[(cb*16 + ks + t3 + 4)*LDP + rb + 8];
            }
#pragma unroll
            for (int nt = 0; nt < 8; nt++) {
                uint32_t bb[2];
                bb[0] = Bs[(ks + t3)*LDP + n0 + nt*8 + g];
                bb[1] = Bs[(ks + t3 + 4)*LDP + n0 + nt*8 + g];
                mma_tf32(acc3[0][nt], a[0], bb);
                mma_tf32(acc3[1][nt], a[1], bb);
            }
        }
    }
    __syncthreads();   // all warps done reading Vs

    // epilogue 2: bn3a/relu/bn3b -> Fs[c][pos] (f32), then +identity coalesced store
    float* Fs = smf + SMF_V;
#pragma unroll
    for (int nt = 0; nt < 8; nt++) {
        int c0 = n0 + nt*8 + 2*t3;
        float sa0 = __ldg(s3a + c0),     ta0 = __ldg(t3a + c0);
        float sb0 = __ldg(s3b + c0),     tb0 = __ldg(t3b + c0);
        float sa1 = __ldg(s3a + c0 + 1), ta1 = __ldg(t3a + c0 + 1);
        float sb1 = __ldg(s3b + c0 + 1), tb1 = __ldg(t3b + c0 + 1);
#pragma unroll
        for (int mt = 0; mt < 2; mt++) {
            int plo = m0 + mt*16 + g;
            Fs[c0*LDP + plo]           = fmaxf(acc3[mt][nt][0] * sa0 + ta0, 0.f) * sb0 + tb0;
            Fs[(c0 + 1)*LDP + plo]     = fmaxf(acc3[mt][nt][1] * sa1 + ta1, 0.f) * sb1 + tb1;
            Fs[c0*LDP + plo + 8]       = fmaxf(acc3[mt][nt][2] * sa0 + ta0, 0.f) * sb0 + tb0;
            Fs[(c0 + 1)*LDP + plo + 8] = fmaxf(acc3[mt][nt][3] * sa1 + ta1, 0.f) * sb1 + tb1;
        }
    }
    __syncthreads();

    {
        const int o2 = tid & 127;
        const int ph = tid >> 7;
        size_t base = ((size_t)(b*PL + o2))*HW + pim0 + ph*64;
        const float* frow = Fs + o2*LDP + ph*64;
#pragma unroll
        for (int i = 0; i < 16; i++) {
            float4 f = *(const float4*)&frow[i*4];
            float4 id = *(const float4*)&g_ident[base + i*4];
            *(float4*)&out[base + i*4] = make_float4(
                fmaxf(f.x + id.x, 0.f), fmaxf(f.y + id.y, 0.f),
                fmaxf(f.z + id.z, 0.f), fmaxf(f.w + id.w, 0.f));
        }
    }
}

// ---------------- host ----------------
extern "C" void kernel_launch(void* const* d_in, const int* in_sizes, int n_in,
                              void* d_out, int out_size) {
    const float* x    = (const float*)d_in[0];
    const float* w1   = (const float*)d_in[1];
    const float* s1a  = (const float*)d_in[2];
    const float* t1a  = (const float*)d_in[3];
    const float* s1b  = (const float*)d_in[4];
    const float* t1b  = (const float*)d_in[5];
    const float* w_off= (const float*)d_in[6];
    const float* b_off= (const float*)d_in[7];
    const float* w_dc = (const float*)d_in[8];
    const float* b_dc = (const float*)d_in[9];
    const float* s2   = (const float*)d_in[10];
    const float* t2   = (const float*)d_in[11];
    const float* w3   = (const float*)d_in[12];
    const float* s3a  = (const float*)d_in[13];
    const float* t3a  = (const float*)d_in[14];
    const float* s3b  = (const float*)d_in[15];
    const float* t3b  = (const float*)d_in[16];
    const float* w_ds = (const float*)d_in[17];
    const float* b_ds = (const float*)d_in[18];
    const float* sd   = (const float*)d_in[19];
    const float* td   = (const float*)d_in[20];
    float* out = (float*)d_out;

    k_prep<<<(CK*PL + 255)/256, 256>>>(w_off, w_dc, w3, w1, w_ds);

    dim3 g1(HW/128, 2, NB);
    k_cgemm<<<g1, 256>>>(x, s1a, t1a, s1b, t1b, b_ds, sd, td);

    dim3 g2(HH, NB);
    k_offset<<<g2, 128>>>(b_off);

    cudaFuncSetAttribute(k_dgemm, cudaFuncAttributeMaxDynamicSharedMemorySize, SMEM_TOT);
    k_dgemm<<<NB*HW/128, 256, SMEM_TOT>>>(b_dc, s2, t2, s3a, t3a, s3b, t3b, out);
}

// round 6
// speedup vs baseline: 2.7858x; 2.0769x over previous
#include <cuda_runtime.h>
#include <cstdint>
#include <math.h>

#define NB  4
#define CIN 256
#define PL  128
#define HH  128
#define WW  128
#define HW  16384
#define KK  9
#define CK  1152   // PL*KK
#define LDP 136

// ---- scratch (device globals: allocation-free) ----
__device__ float g_out1_nchw[NB*PL*HW];
__device__ float g_out1_nhwc[NB*HW*PL];
__device__ float g_ident[NB*PL*HW];
__device__ float g_py[NB*KK*HW];
__device__ float g_px[NB*KK*HW];
__device__ float g_mk[NB*KK*HW];
__device__ float g_wOffP[CK*32];          // [tap*128+c][o<27 pad 32] (tf32 bits)
__device__ float g_wDcB[CK*PL];           // [K'=k*128+c][o]          (tf32 bits)
__device__ float g_w3T[PL*PL];            // [c][o]                   (tf32 bits)
__device__ float g_w1T[CIN*PL];           // [c][o]                   (tf32 bits)
__device__ float g_wdsT[CIN*PL];          // [c][o]                   (tf32 bits)

// ---- tf32 mma helpers ----
__device__ __forceinline__ uint32_t f2tf(float x) {
    uint32_t r; asm("cvt.rna.tf32.f32 %0, %1;" : "=r"(r) : "f"(x)); return r;
}
__device__ __forceinline__ void mma_tf32(float d[4], const uint32_t a[4], const uint32_t b[2]) {
    asm volatile("mma.sync.aligned.m16n8k8.row.col.f32.tf32.tf32.f32 "
        "{%0,%1,%2,%3}, {%4,%5,%6,%7}, {%8,%9}, {%0,%1,%2,%3};"
        : "+f"(d[0]), "+f"(d[1]), "+f"(d[2]), "+f"(d[3])
        : "r"(a[0]), "r"(a[1]), "r"(a[2]), "r"(a[3]), "r"(b[0]), "r"(b[1]));
}

// ---------------- K0: weight transposes + tf32 conversion ----------------
__global__ void k_prep(const float* __restrict__ w_off,
                       const float* __restrict__ w_dc,
                       const float* __restrict__ w3,
                       const float* __restrict__ w1,
                       const float* __restrict__ wds) {
    int i = blockIdx.x * blockDim.x + threadIdx.x;
    if (i < CK*32) {
        int row = i >> 5, o = i & 31;
        int tap = row >> 7, c = row & 127;
        g_wOffP[i] = (o < 27) ? __uint_as_float(f2tf(w_off[o*CK + c*KK + tap])) : 0.f;
    }
    if (i < CK*PL) {
        int o = i & 127, t = i >> 7;
        int c = t & 127, k = t >> 7;
        g_wDcB[i] = __uint_as_float(f2tf(w_dc[(o*PL + c)*KK + k]));
    }
    if (i < CIN*PL) {
        int c = i >> 7, o = i & 127;
        g_w1T[i]  = __uint_as_float(f2tf(w1[o*CIN + c]));
        g_wdsT[i] = __uint_as_float(f2tf(wds[o*CIN + c]));
    }
    if (i < PL*PL) {
        int c = i >> 7, o = i & 127;
        g_w3T[i] = __uint_as_float(f2tf(w3[o*PL + c]));
    }
}

// ---------------- K1: conv1 / downsample via tf32 mma ----------------
// SMEM: A[2][16*136] @0, B[2][16*136] @4352 ; Fs[128*136] @0 (reuse). 17408 floats.
#define SMEM_TOT_C (17408 * 4)
__global__ __launch_bounds__(256, 2) void k_cgemm(
    const float* __restrict__ x,
    const float* __restrict__ s1a, const float* __restrict__ t1a,
    const float* __restrict__ s1b, const float* __restrict__ t1b,
    const float* __restrict__ bds, const float* __restrict__ sd, const float* __restrict__ td)
{
    extern __shared__ __align__(16) float smf[];

    const int tid  = threadIdx.x;
    const int wrp  = tid >> 5;
    const int t3   = tid & 3;
    const int g    = (tid & 31) >> 2;
    const int m0   = (wrp & 3) * 32;
    const int n0   = (wrp >> 2) * 64;
    const int pos0 = blockIdx.x * 128;
    const int job  = blockIdx.y;
    const int b    = blockIdx.z;
    const float* wT = job ? g_wdsT : g_w1T;
    const float* xb = x + (size_t)b * CIN * HW + pos0;

    float acc[2][8][4];
#pragma unroll
    for (int mt = 0; mt < 2; mt++)
#pragma unroll
        for (int nt = 0; nt < 8; nt++)
#pragma unroll
            for (int i = 0; i < 4; i++) acc[mt][nt][i] = 0.f;

    auto fill = [&](int kc, int bf) {
        float* Ab = smf + bf * 2176;
        float* Bb = smf + 4352 + bf * 2176;
#pragma unroll
        for (int u = 0; u < 2; u++) {
            int q = u*256 + tid, row = q >> 5, col4 = (q & 31) * 4;
            float4 v = *(const float4*)&xb[(size_t)(kc*16 + row) * HW + col4];
            uint4 tv = make_uint4(f2tf(v.x), f2tf(v.y), f2tf(v.z), f2tf(v.w));
            *(uint4*)&Ab[row*LDP + col4] = tv;
            *(float4*)&Bb[row*LDP + col4] = *(const float4*)&wT[(kc*16 + row)*PL + col4];
        }
    };

    fill(0, 0);
    __syncthreads();

    for (int kc = 0; kc < 16; kc++) {
        if (kc < 15) fill(kc + 1, (kc + 1) & 1);
        const uint32_t* As = (const uint32_t*)(smf + (kc & 1) * 2176);
        const uint32_t* Bs = (const uint32_t*)(smf + 4352 + (kc & 1) * 2176);
#pragma unroll
        for (int ks = 0; ks < 16; ks += 8) {
            uint32_t a[2][4];
#pragma unroll
            for (int mt = 0; mt < 2; mt++) {
                int rb = m0 + mt*16 + g;
                a[mt][0] = As[(ks + t3)*LDP + rb];
                a[mt][1] = As[(ks + t3)*LDP + rb + 8];
                a[mt][2] = As[(ks + t3 + 4)*LDP + rb];
                a[mt][3] = As[(ks + t3 + 4)*LDP + rb + 8];
            }
#pragma unroll
            for (int nt = 0; nt < 8; nt++) {
                uint32_t bb[2];
                bb[0] = Bs[(ks + t3)*LDP + n0 + nt*8 + g];
                bb[1] = Bs[(ks + t3 + 4)*LDP + n0 + nt*8 + g];
                mma_tf32(acc[0][nt], a[0], bb);
                mma_tf32(acc[1][nt], a[1], bb);
            }
        }
        __syncthreads();
    }

    // stage post-BN values into Fs[c][pos]
    float* Fs = smf;
#pragma unroll
    for (int nt = 0; nt < 8; nt++) {
        int c0 = n0 + nt*8 + 2*t3;
        float p0a, p0b, p0c, p0d, p1a, p1b, p1c, p1d;
        if (job == 0) {
            p0a = __ldg(s1a + c0);     p0b = __ldg(t1a + c0);
            p0c = __ldg(s1b + c0);     p0d = __ldg(t1b + c0);
            p1a = __ldg(s1a + c0 + 1); p1b = __ldg(t1a + c0 + 1);
            p1c = __ldg(s1b + c0 + 1); p1d = __ldg(t1b + c0 + 1);
        } else {
            p0a = __ldg(bds + c0);     p0b = __ldg(sd + c0);     p0c = __ldg(td + c0);
            p1a = __ldg(bds + c0 + 1); p1b = __ldg(sd + c0 + 1); p1c = __ldg(td + c0 + 1);
            p0d = p1d = 0.f;
        }
#pragma unroll
        for (int mt = 0; mt < 2; mt++) {
            int plo = m0 + mt*16 + g;
            float v0 = acc[mt][nt][0], v1 = acc[mt][nt][1];
            float v2 = acc[mt][nt][2], v3 = acc[mt][nt][3];
            if (job == 0) {
                v0 = fmaxf(fmaxf(v0 * p0a + p0b, 0.f) * p0c + p0d, 0.f);
                v2 = fmaxf(fmaxf(v2 * p0a + p0b, 0.f) * p0c + p0d, 0.f);
                v1 = fmaxf(fmaxf(v1 * p1a + p1b, 0.f) * p1c + p1d, 0.f);
                v3 = fmaxf(fmaxf(v3 * p1a + p1b, 0.f) * p1c + p1d, 0.f);
            } else {
                v0 = (v0 + p0a) * p0b + p0c;  v2 = (v2 + p0a) * p0b + p0c;
                v1 = (v1 + p1a) * p1b + p1c;  v3 = (v3 + p1a) * p1b + p1c;
            }
            Fs[c0*LDP + plo]           = v0;
            Fs[(c0 + 1)*LDP + plo]     = v1;
            Fs[c0*LDP + plo + 8]       = v2;
            Fs[(c0 + 1)*LDP + plo + 8] = v3;
        }
    }
    __syncthreads();

    const int o2 = tid & 127;
    const int ph = tid >> 7;
    float* dstN = (job == 0) ? g_out1_nchw : g_ident;
    {
        size_t base = ((size_t)(b*PL + o2))*HW + pos0 + ph*64;
        const float* frow = Fs + o2*LDP + ph*64;
#pragma unroll
        for (int i = 0; i < 16; i++)
            *(float4*)&dstN[base + i*4] = *(const float4*)&frow[i*4];
    }
    if (job == 0) {
        // NHWC: thread = position o2, channel half ph
        size_t base = ((size_t)(b*HW + pos0 + o2))*PL + ph*64;
#pragma unroll
        for (int i = 0; i < 16; i++) {
            int c = ph*64 + i*4;
            float4 v = make_float4(Fs[c*LDP + o2], Fs[(c+1)*LDP + o2],
                                   Fs[(c+2)*LDP + o2], Fs[(c+3)*LDP + o2]);
            *(float4*)&g_out1_nhwc[base + i*4] = v;
        }
    }
}

// ---------------- K2: offset/mask 3x3 conv via tf32 mma (im2col GEMM) ----------------
#define OLDB 40
__global__ __launch_bounds__(256) void k_offset(const float* __restrict__ b_off) {
    __shared__ __align__(16) float Ao[2][16*LDP];    // 2x2176
    __shared__ __align__(16) float Bo[2][16*OLDB];   // 2x640
    __shared__ __align__(16) float So[32*LDP];       // 4352

    const int tid = threadIdx.x;
    const int wrp = tid >> 5;
    const int t3  = tid & 3;
    const int g   = (tid & 31) >> 2;
    const int m0  = wrp * 16;
    const int h   = blockIdx.x;
    const int b   = blockIdx.y;
    const float* inb = g_out1_nchw + (size_t)b * PL * HW;

    float acc[4][4];
#pragma unroll
    for (int nt = 0; nt < 4; nt++)
#pragma unroll
        for (int i = 0; i < 4; i++) acc[nt][i] = 0.f;

    auto fill = [&](int kc, int bf) {
        const int tap = (kc*16) >> 7;
        const int c0  = (kc*16) & 127;
        const int ky  = tap / 3;
        const int kx  = tap - 3*ky;
        const int yy  = h + ky - 1;
        const bool rv = ((unsigned)yy < HH);
#pragma unroll
        for (int u = 0; u < 8; u++) {
            int idx = u*256 + tid;
            int kr = idx >> 7, p = idx & 127;
            int xp = p + kx - 1;
            float v = 0.f;
            if (rv && (unsigned)xp < WW)
                v = inb[(size_t)(c0 + kr)*HW + yy*WW + xp];
            Ao[bf][kr*LDP + p] = __uint_as_float(f2tf(v));
        }
#pragma unroll
        for (int u = 0; u < 2; u++) {
            int idx = u*256 + tid;
            int kr = idx >> 5, o = idx & 31;
            Bo[bf][kr*OLDB + o] = g_wOffP[(size_t)(kc*16 + kr)*32 + o];
        }
    };

    fill(0, 0);
    __syncthreads();

    for (int kc = 0; kc < 72; kc++) {
        if (kc < 71) fill(kc + 1, (kc + 1) & 1);
        const uint32_t* As = (const uint32_t*)Ao[kc & 1];
        const uint32_t* Bs = (const uint32_t*)Bo[kc & 1];
#pragma unroll
        for (int ks = 0; ks < 16; ks += 8) {
            uint32_t a[4];
            a[0] = As[(ks + t3)*LDP + m0 + g];
            a[1] = As[(ks + t3)*LDP + m0 + g + 8];
            a[2] = As[(ks + t3 + 4)*LDP + m0 + g];
            a[3] = As[(ks + t3 + 4)*LDP + m0 + g + 8];
#pragma unroll
            for (int nt = 0; nt < 4; nt++) {
                uint32_t bb[2];
                bb[0] = Bs[(ks + t3)*OLDB + nt*8 + g];
                bb[1] = Bs[(ks + t3 + 4)*OLDB + nt*8 + g];
                mma_tf32(acc[nt], a, bb);
            }
        }
        __syncthreads();
    }

    // stage conv outputs So[o][p]
#pragma unroll
    for (int nt = 0; nt < 4; nt++) {
        int c0 = nt*8 + 2*t3;
        int plo = m0 + g;
        So[c0*LDP + plo]           = acc[nt][0];
        So[(c0 + 1)*LDP + plo]     = acc[nt][1];
        So[c0*LDP + plo + 8]       = acc[nt][2];
        So[(c0 + 1)*LDP + plo + 8] = acc[nt][3];
    }
    __syncthreads();

    const int p = tid & 127;
    const int half = tid >> 7;
    for (int k = half; k < 9; k += 2) {
        float dy = So[k*LDP + p]        + __ldg(b_off + k);
        float dx = So[(9 + k)*LDP + p]  + __ldg(b_off + 9 + k);
        float z  = So[(18 + k)*LDP + p] + __ldg(b_off + 18 + k);
        float mk = 1.f / (1.f + expf(-z));
        int idx = (b*KK + k)*HW + h*WW + p;
        g_py[idx] = (float)(h - 1 + k/3) + dy;
        g_px[idx] = (float)(p - 1 + k%3) + dx;
        g_mk[idx] = mk;
    }
}

// ---------------- K3: deform GEMM via tf32 mma + conv3 + residual (unchanged R5) ----------------
#define SMF_A   0
#define SMF_B   4352
#define SMF_CY  8704
#define SMF_CX  (SMF_CY + 1152)
#define SMF_CM  (SMF_CX + 1152)
#define SMF_V   0
#define SMF_B2  17408
#define SMEM_TOT (19584 * 4)

__device__ __forceinline__ void gather8(const float* __restrict__ nhwc,
                                        const float* cY, const float* cX, const float* cM,
                                        int tap, int pos, int cbase, float st[8]) {
    int ci = tap*128 + pos;
    float py = cY[ci], px = cX[ci], mk = cM[ci];
    float fy = floorf(py), fx = floorf(px);
    float wy = py - fy, wx = px - fx;
    int y0 = (int)fy, x0 = (int)fx;
    bool y0k = ((unsigned)y0 < HH), y1k = ((unsigned)(y0+1) < HH);
    bool x0k = ((unsigned)x0 < WW), x1k = ((unsigned)(x0+1) < WW);
    float w00 = (1.f-wy)*(1.f-wx)*mk, w01 = (1.f-wy)*wx*mk;
    float w10 = wy*(1.f-wx)*mk,       w11 = wy*wx*mk;
    const float* p00 = nhwc + ((long)y0*WW + x0)*PL + cbase;
    float4 z = make_float4(0.f, 0.f, 0.f, 0.f);
    bool v00 = y0k && x0k, v01 = y0k && x1k, v10 = y1k && x0k, v11 = y1k && x1k;
    float4 q00a = v00 ? *(const float4*)p00 : z;
    float4 q00b = v00 ? *(const float4*)(p00 + 4) : z;
    float4 q01a = v01 ? *(const float4*)(p00 + PL) : z;
    float4 q01b = v01 ? *(const float4*)(p00 + PL + 4) : z;
    float4 q10a = v10 ? *(const float4*)(p00 + WW*PL) : z;
    float4 q10b = v10 ? *(const float4*)(p00 + WW*PL + 4) : z;
    float4 q11a = v11 ? *(const float4*)(p00 + WW*PL + PL) : z;
    float4 q11b = v11 ? *(const float4*)(p00 + WW*PL + PL + 4) : z;
    st[0] = q00a.x*w00 + q01a.x*w01 + q10a.x*w10 + q11a.x*w11;
    st[1] = q00a.y*w00 + q01a.y*w01 + q10a.y*w10 + q11a.y*w11;
    st[2] = q00a.z*w00 + q01a.z*w01 + q10a.z*w10 + q11a.z*w11;
    st[3] = q00a.w*w00 + q01a.w*w01 + q10a.w*w10 + q11a.w*w11;
    st[4] = q00b.x*w00 + q01b.x*w01 + q10b.x*w10 + q11b.x*w11;
    st[5] = q00b.y*w00 + q01b.y*w01 + q10b.y*w10 + q11b.y*w11;
    st[6] = q00b.z*w00 + q01b.z*w01 + q10b.z*w10 + q11b.z*w11;
    st[7] = q00b.w*w00 + q01b.w*w01 + q10b.w*w10 + q11b.w*w11;
}

__global__ __launch_bounds__(256, 2) void k_dgemm(
    const float* __restrict__ b_dc, const float* __restrict__ s2, const float* __restrict__ t2,
    const float* __restrict__ s3a, const float* __restrict__ t3a,
    const float* __restrict__ s3b, const float* __restrict__ t3b,
    float* __restrict__ out)
{
    extern __shared__ __align__(16) float smf[];
    float* cY = smf + SMF_CY;
    float* cX = smf + SMF_CX;
    float* cM = smf + SMF_CM;

    const int tid  = threadIdx.x;
    const int wrp  = tid >> 5;
    const int t3   = tid & 3;
    const int g    = (tid & 31) >> 2;
    const int m0   = (wrp & 3) * 32;
    const int n0   = (wrp >> 2) * 64;
    const int gpos = tid >> 1;
    const int cg   = (tid & 1) * 8;
    const int bkk  = (tid*2) >> 5;
    const int bo4  = ((tid*2) & 31) * 4;
    const int pos0 = blockIdx.x * 128;
    const int b    = pos0 >> 14;
    const int pim0 = pos0 & (HW - 1);

    for (int idx = tid; idx < 1152; idx += 256) {
        int k = idx >> 7, p = idx & 127;
        int gidx = (b*KK + k)*HW + pim0 + p;
        cY[idx] = g_py[gidx]; cX[idx] = g_px[gidx]; cM[idx] = g_mk[gidx];
    }
    __syncthreads();

    const float* nhwc = g_out1_nhwc + (size_t)b * HW * PL;

    float acc[2][8][4];
#pragma unroll
    for (int mt = 0; mt < 2; mt++)
#pragma unroll
        for (int nt = 0; nt < 8; nt++)
#pragma unroll
            for (int i = 0; i < 4; i++) acc[mt][nt][i] = 0.f;

    auto fill = [&](int kc, int bf) {
        float st[8];
        gather8(nhwc, cY, cX, cM, kc >> 3, gpos, ((kc & 7) << 4) + cg, st);
        float* Ab = smf + SMF_A + bf * 2176;
        float* Bb = smf + SMF_B + bf * 2176;
#pragma unroll
        for (int j = 0; j < 8; j++)
            Ab[(cg + j)*LDP + gpos] = __uint_as_float(f2tf(st[j]));
        const float* src = g_wDcB + ((size_t)kc*16 + bkk)*PL + bo4;
        *(float4*)&Bb[bkk*LDP + bo4]     = *(const float4*)src;
        *(float4*)&Bb[bkk*LDP + bo4 + 4] = *(const float4*)(src + 4);
    };

    fill(0, 0);
    __syncthreads();

    for (int kc = 0; kc < 72; kc++) {
        if (kc < 71) fill(kc + 1, (kc + 1) & 1);
        const uint32_t* As = (const uint32_t*)(smf + SMF_A + (kc & 1) * 2176);
        const uint32_t* Bs = (const uint32_t*)(smf + SMF_B + (kc & 1) * 2176);
#pragma unroll
        for (int ks = 0; ks < 16; ks += 8) {
            uint32_t a[2][4];
#pragma unroll
            for (int mt = 0; mt < 2; mt++) {
                int rb = m0 + mt*16 + g;
                a[mt][0] = As[(ks + t3)*LDP + rb];
                a[mt][1] = As[(ks + t3)*LDP + rb + 8];
                a[mt][2] = As[(ks + t3 + 4)*LDP + rb];
                a[mt][3] = As[(ks + t3 + 4)*LDP + rb + 8];
            }
#pragma unroll
            for (int nt = 0; nt < 8; nt++) {
                uint32_t bb[2];
                bb[0] = Bs[(ks + t3)*LDP + n0 + nt*8 + g];
                bb[1] = Bs[(ks + t3 + 4)*LDP + n0 + nt*8 + g];
                mma_tf32(acc[0][nt], a[0], bb);
                mma_tf32(acc[1][nt], a[1], bb);
            }
        }
        __syncthreads();
    }

    float* Vs = smf + SMF_V;
#pragma unroll
    for (int nt = 0; nt < 8; nt++) {
        int c0 = n0 + nt*8 + 2*t3;
        float b0 = __ldg(b_dc + c0),     ss0 = __ldg(s2 + c0),     tt0 = __ldg(t2 + c0);
        float b1 = __ldg(b_dc + c0 + 1), ss1 = __ldg(s2 + c0 + 1), tt1 = __ldg(t2 + c0 + 1);
#pragma unroll
        for (int mt = 0; mt < 2; mt++) {
            int plo = m0 + mt*16 + g;
            float v0 = fmaxf((acc[mt][nt][0] + b0) * ss0 + tt0, 0.f);
            float v1 = fmaxf((acc[mt][nt][1] + b1) * ss1 + tt1, 0.f);
            float v2 = fmaxf((acc[mt][nt][2] + b0) * ss0 + tt0, 0.f);
            float v3 = fmaxf((acc[mt][nt][3] + b1) * ss1 + tt1, 0.f);
            Vs[c0*LDP + plo]           = __uint_as_float(f2tf(v0));
            Vs[(c0 + 1)*LDP + plo]     = __uint_as_float(f2tf(v1));
            Vs[c0*LDP + plo + 8]       = __uint_as_float(f2tf(v2));
            Vs[(c0 + 1)*LDP + plo + 8] = __uint_as_float(f2tf(v3));
        }
    }
    __syncthreads();

    float acc3[2][8][4];
#pragma unroll
    for (int mt = 0; mt < 2; mt++)
#pragma unroll
        for (int nt = 0; nt < 8; nt++)
#pragma unroll
            for (int i = 0; i < 4; i++) acc3[mt][nt][i] = 0.f;

    float* B2 = smf + SMF_B2;
    for (int cb = 0; cb < 8; cb++) {
        float4 r[2];
#pragma unroll
        for (int u = 0; u < 2; u++) {
            int q = u*256 + tid, rr = q >> 5, col4 = (q & 31) * 4;
            r[u] = *(const float4*)&g_w3T[((size_t)cb*16 + rr)*PL + col4];
        }
        __syncthreads();
#pragma unroll
        for (int u = 0; u < 2; u++) {
            int q = u*256 + tid, rr = q >> 5, col4 = (q & 31) * 4;
            *(float4*)&B2[rr*LDP + col4] = r[u];
        }
        __syncthreads();
        const uint32_t* As = (const uint32_t*)Vs;
        const uint32_t* Bs = (const uint32_t*)B2;
#pragma unroll
        for (int ks = 0; ks < 16; ks += 8) {
            uint32_t a[2][4];
#pragma unroll
            for (int mt = 0; mt < 2; mt++) {
                int rb = m0 + mt*16 + g;
                a[mt][0] = As[(cb*16 + ks + t3)*LDP + rb];
                a[mt][1] = As[(cb*16 + ks + t3)*LDP + rb + 8];
                a[mt][2] = As[(cb*16 + ks + t3 + 4)*LDP + rb];
                a[mt][3] = As[(cb*16 + ks + t3 + 4)*LDP + rb + 8];
            }
#pragma unroll
            for (int nt = 0; nt < 8; nt++) {
                uint32_t bb[2];
                bb[0] = Bs[(ks + t3)*LDP + n0 + nt*8 + g];
                bb[1] = Bs[(ks + t3 + 4)*LDP + n0 + nt*8 + g];
                mma_tf32(acc3[0][nt], a[0], bb);
                mma_tf32(acc3[1][nt], a[1], bb);
            }
        }
    }
    __syncthreads();

    float* Fs = smf + SMF_V;
#pragma unroll
    for (int nt = 0; nt < 8; nt++) {
        int c0 = n0 + nt*8 + 2*t3;
        float sa0 = __ldg(s3a + c0),     ta0 = __ldg(t3a + c0);
        float sb0 = __ldg(s3b + c0),     tb0 = __ldg(t3b + c0);
        float sa1 = __ldg(s3a + c0 + 1), ta1 = __ldg(t3a + c0 + 1);
        float sb1 = __ldg(s3b + c0 + 1), tb1 = __ldg(t3b + c0 + 1);
#pragma unroll
        for (int mt = 0; mt < 2; mt++) {
            int plo = m0 + mt*16 + g;
            Fs[c0*LDP + plo]           = fmaxf(acc3[mt][nt][0] * sa0 + ta0, 0.f) * sb0 + tb0;
            Fs[(c0 + 1)*LDP + plo]     = fmaxf(acc3[mt][nt][1] * sa1 + ta1, 0.f) * sb1 + tb1;
            Fs[c0*LDP + plo + 8]       = fmaxf(acc3[mt][nt][2] * sa0 + ta0, 0.f) * sb0 + tb0;
            Fs[(c0 + 1)*LDP + plo + 8] = fmaxf(acc3[mt][nt][3] * sa1 + ta1, 0.f) * sb1 + tb1;
        }
    }
    __syncthreads();

    {
        const int o2 = tid & 127;
        const int ph = tid >> 7;
        size_t base = ((size_t)(b*PL + o2))*HW + pim0 + ph*64;
        const float* frow = Fs + o2*LDP + ph*64;
#pragma unroll
        for (int i = 0; i < 16; i++) {
            float4 f = *(const float4*)&frow[i*4];
            float4 id = *(const float4*)&g_ident[base + i*4];
            *(float4*)&out[base + i*4] = make_float4(
                fmaxf(f.x + id.x, 0.f), fmaxf(f.y + id.y, 0.f),
                fmaxf(f.z + id.z, 0.f), fmaxf(f.w + id.w, 0.f));
        }
    }
}

// ---------------- host ----------------
extern "C" void kernel_launch(void* const* d_in, const int* in_sizes, int n_in,
                              void* d_out, int out_size) {
    const float* x    = (const float*)d_in[0];
    const float* w1   = (const float*)d_in[1];
    const float* s1a  = (const float*)d_in[2];
    const float* t1a  = (const float*)d_in[3];
    const float* s1b  = (const float*)d_in[4];
    const float* t1b  = (const float*)d_in[5];
    const float* w_off= (const float*)d_in[6];
    const float* b_off= (const float*)d_in[7];
    const float* w_dc = (const float*)d_in[8];
    const float* b_dc = (const float*)d_in[9];
    const float* s2   = (const float*)d_in[10];
    const float* t2   = (const float*)d_in[11];
    const float* w3   = (const float*)d_in[12];
    const float* s3a  = (const float*)d_in[13];
    const float* t3a  = (const float*)d_in[14];
    const float* s3b  = (const float*)d_in[15];
    const float* t3b  = (const float*)d_in[16];
    const float* w_ds = (const float*)d_in[17];
    const float* b_ds = (const float*)d_in[18];
    const float* sd   = (const float*)d_in[19];
    const float* td   = (const float*)d_in[20];
    float* out = (float*)d_out;

    k_prep<<<(CK*PL + 255)/256, 256>>>(w_off, w_dc, w3, w1, w_ds);

    cudaFuncSetAttribute(k_cgemm, cudaFuncAttributeMaxDynamicSharedMemorySize, SMEM_TOT_C);
    dim3 g1(HW/128, 2, NB);
    k_cgemm<<<g1, 256, SMEM_TOT_C>>>(x, s1a, t1a, s1b, t1b, b_ds, sd, td);

    dim3 g2(HH, NB);
    k_offset<<<g2, 256>>>(b_off);

    cudaFuncSetAttribute(k_dgemm, cudaFuncAttributeMaxDynamicSharedMemorySize, SMEM_TOT);
    k_dgemm<<<NB*HW/128, 256, SMEM_TOT>>>(b_dc, s2, t2, s3a, t3a, s3b, t3b, out);
}

// round 7
// speedup vs baseline: 2.8010x; 1.0055x over previous
#include <cuda_runtime.h>
#include <cstdint>
#include <math.h>

#define NB  4
#define CIN 256
#define PL  128
#define HH  128
#define WW  128
#define HW  16384
#define KK  9
#define CK  1152   // PL*KK
#define LDP 136

// ---- scratch (device globals: allocation-free) ----
__device__ float g_out1_nchw[NB*PL*HW];
__device__ float g_out1_nhwc[NB*HW*PL];
__device__ float g_ident[NB*PL*HW];
__device__ float g_py[NB*KK*HW];
__device__ float g_px[NB*KK*HW];
__device__ float g_mk[NB*KK*HW];
__device__ float g_wOffP[CK*32];          // [tap*128+c][o<27 pad 32] (tf32 bits)
__device__ float g_wDcB[CK*PL];           // [K'=k*128+c][o]          (tf32 bits)
__device__ float g_w3T[PL*PL];            // [c][o]                   (tf32 bits)
__device__ float g_w1T[CIN*PL];           // [c][o]                   (tf32 bits)
__device__ float g_wdsT[CIN*PL];          // [c][o]                   (tf32 bits)

// ---- tf32 mma helpers ----
__device__ __forceinline__ uint32_t f2tf(float x) {
    uint32_t r; asm("cvt.rna.tf32.f32 %0, %1;" : "=r"(r) : "f"(x)); return r;
}
__device__ __forceinline__ void mma_tf32(float d[4], const uint32_t a[4], const uint32_t b[2]) {
    asm volatile("mma.sync.aligned.m16n8k8.row.col.f32.tf32.tf32.f32 "
        "{%0,%1,%2,%3}, {%4,%5,%6,%7}, {%8,%9}, {%0,%1,%2,%3};"
        : "+f"(d[0]), "+f"(d[1]), "+f"(d[2]), "+f"(d[3])
        : "r"(a[0]), "r"(a[1]), "r"(a[2]), "r"(a[3]), "r"(b[0]), "r"(b[1]));
}

// ---------------- K0: weight transposes + tf32 conversion ----------------
__global__ void k_prep(const float* __restrict__ w_off,
                       const float* __restrict__ w_dc,
                       const float* __restrict__ w3,
                       const float* __restrict__ w1,
                       const float* __restrict__ wds) {
    int i = blockIdx.x * blockDim.x + threadIdx.x;
    if (i < CK*32) {
        int row = i >> 5, o = i & 31;
        int tap = row >> 7, c = row & 127;
        g_wOffP[i] = (o < 27) ? __uint_as_float(f2tf(w_off[o*CK + c*KK + tap])) : 0.f;
    }
    if (i < CK*PL) {
        int o = i & 127, t = i >> 7;
        int c = t & 127, k = t >> 7;
        g_wDcB[i] = __uint_as_float(f2tf(w_dc[(o*PL + c)*KK + k]));
    }
    if (i < CIN*PL) {
        int c = i >> 7, o = i & 127;
        g_w1T[i]  = __uint_as_float(f2tf(w1[o*CIN + c]));
        g_wdsT[i] = __uint_as_float(f2tf(wds[o*CIN + c]));
    }
    if (i < PL*PL) {
        int c = i >> 7, o = i & 127;
        g_w3T[i] = __uint_as_float(f2tf(w3[o*PL + c]));
    }
}

// ---------------- K1: conv1 / downsample via tf32 mma (pipelined) ----------------
#define SMEM_TOT_C (17408 * 4)
__global__ __launch_bounds__(256, 2) void k_cgemm(
    const float* __restrict__ x,
    const float* __restrict__ s1a, const float* __restrict__ t1a,
    const float* __restrict__ s1b, const float* __restrict__ t1b,
    const float* __restrict__ bds, const float* __restrict__ sd, const float* __restrict__ td)
{
    extern __shared__ __align__(16) float smf[];

    const int tid  = threadIdx.x;
    const int wrp  = tid >> 5;
    const int t3   = tid & 3;
    const int g    = (tid & 31) >> 2;
    const int m0   = (wrp & 3) * 32;
    const int n0   = (wrp >> 2) * 64;
    const int pos0 = blockIdx.x * 128;
    const int job  = blockIdx.y;
    const int b    = blockIdx.z;
    const float* wT = job ? g_wdsT : g_w1T;
    const float* xb = x + (size_t)b * CIN * HW + pos0;

    float acc[2][8][4];
#pragma unroll
    for (int mt = 0; mt < 2; mt++)
#pragma unroll
        for (int nt = 0; nt < 8; nt++)
#pragma unroll
            for (int i = 0; i < 4; i++) acc[mt][nt][i] = 0.f;

    float4 sa[2], sb[2];
    const int lrow = tid >> 5;
    const int lc4a = (tid & 31) * 4;
    auto ld = [&](int kc) {
#pragma unroll
        for (int u = 0; u < 2; u++) {
            int row = lrow + u*8;
            sa[u] = *(const float4*)&xb[(size_t)(kc*16 + row) * HW + lc4a];
            sb[u] = *(const float4*)&wT[(kc*16 + row)*PL + lc4a];
        }
    };
    auto sts = [&](int bf) {
        float* Ab = smf + bf * 2176;
        float* Bb = smf + 4352 + bf * 2176;
#pragma unroll
        for (int u = 0; u < 2; u++) {
            int row = lrow + u*8;
            uint4 tv = make_uint4(f2tf(sa[u].x), f2tf(sa[u].y), f2tf(sa[u].z), f2tf(sa[u].w));
            *(uint4*)&Ab[row*LDP + lc4a] = tv;
            *(float4*)&Bb[row*LDP + lc4a] = sb[u];
        }
    };

    ld(0); sts(0);
    __syncthreads();

    for (int kc = 0; kc < 16; kc++) {
        if (kc < 15) ld(kc + 1);
        const uint32_t* As = (const uint32_t*)(smf + (kc & 1) * 2176);
        const uint32_t* Bs = (const uint32_t*)(smf + 4352 + (kc & 1) * 2176);
#pragma unroll
        for (int ks = 0; ks < 16; ks += 8) {
            uint32_t a[2][4];
#pragma unroll
            for (int mt = 0; mt < 2; mt++) {
                int rb = m0 + mt*16 + g;
                a[mt][0] = As[(ks + t3)*LDP + rb];
                a[mt][1] = As[(ks + t3)*LDP + rb + 8];
                a[mt][2] = As[(ks + t3 + 4)*LDP + rb];
                a[mt][3] = As[(ks + t3 + 4)*LDP + rb + 8];
            }
#pragma unroll
            for (int nt = 0; nt < 8; nt++) {
                uint32_t bb[2];
                bb[0] = Bs[(ks + t3)*LDP + n0 + nt*8 + g];
                bb[1] = Bs[(ks + t3 + 4)*LDP + n0 + nt*8 + g];
                mma_tf32(acc[0][nt], a[0], bb);
                mma_tf32(acc[1][nt], a[1], bb);
            }
        }
        if (kc < 15) sts((kc + 1) & 1);
        __syncthreads();
    }

    float* Fs = smf;
#pragma unroll
    for (int nt = 0; nt < 8; nt++) {
        int c0 = n0 + nt*8 + 2*t3;
        float p0a, p0b, p0c, p0d, p1a, p1b, p1c, p1d;
        if (job == 0) {
            p0a = __ldg(s1a + c0);     p0b = __ldg(t1a + c0);
            p0c = __ldg(s1b + c0);     p0d = __ldg(t1b + c0);
            p1a = __ldg(s1a + c0 + 1); p1b = __ldg(t1a + c0 + 1);
            p1c = __ldg(s1b + c0 + 1); p1d = __ldg(t1b + c0 + 1);
        } else {
            p0a = __ldg(bds + c0);     p0b = __ldg(sd + c0);     p0c = __ldg(td + c0);
            p1a = __ldg(bds + c0 + 1); p1b = __ldg(sd + c0 + 1); p1c = __ldg(td + c0 + 1);
            p0d = p1d = 0.f;
        }
#pragma unroll
        for (int mt = 0; mt < 2; mt++) {
            int plo = m0 + mt*16 + g;
            float v0 = acc[mt][nt][0], v1 = acc[mt][nt][1];
            float v2 = acc[mt][nt][2], v3 = acc[mt][nt][3];
            if (job == 0) {
                v0 = fmaxf(fmaxf(v0 * p0a + p0b, 0.f) * p0c + p0d, 0.f);
                v2 = fmaxf(fmaxf(v2 * p0a + p0b, 0.f) * p0c + p0d, 0.f);
                v1 = fmaxf(fmaxf(v1 * p1a + p1b, 0.f) * p1c + p1d, 0.f);
                v3 = fmaxf(fmaxf(v3 * p1a + p1b, 0.f) * p1c + p1d, 0.f);
            } else {
                v0 = (v0 + p0a) * p0b + p0c;  v2 = (v2 + p0a) * p0b + p0c;
                v1 = (v1 + p1a) * p1b + p1c;  v3 = (v3 + p1a) * p1b + p1c;
            }
            Fs[c0*LDP + plo]           = v0;
            Fs[(c0 + 1)*LDP + plo]     = v1;
            Fs[c0*LDP + plo + 8]       = v2;
            Fs[(c0 + 1)*LDP + plo + 8] = v3;
        }
    }
    __syncthreads();

    const int o2 = tid & 127;
    const int ph = tid >> 7;
    float* dstN = (job == 0) ? g_out1_nchw : g_ident;
    {
        size_t base = ((size_t)(b*PL + o2))*HW + pos0 + ph*64;
        const float* frow = Fs + o2*LDP + ph*64;
#pragma unroll
        for (int i = 0; i < 16; i++)
            *(float4*)&dstN[base + i*4] = *(const float4*)&frow[i*4];
    }
    if (job == 0) {
        size_t base = ((size_t)(b*HW + pos0 + o2))*PL + ph*64;
#pragma unroll
        for (int i = 0; i < 16; i++) {
            int c = ph*64 + i*4;
            float4 v = make_float4(Fs[c*LDP + o2], Fs[(c+1)*LDP + o2],
                                   Fs[(c+2)*LDP + o2], Fs[(c+3)*LDP + o2]);
            *(float4*)&g_out1_nhwc[base + i*4] = v;
        }
    }
}

// ---------------- K2: offset/mask 3x3 conv via tf32 mma (pipelined) ----------------
#define OLDB 40
__global__ __launch_bounds__(256) void k_offset(const float* __restrict__ b_off) {
    __shared__ __align__(16) float Ao[2][16*LDP];
    __shared__ __align__(16) float Bo[2][16*OLDB];
    __shared__ __align__(16) float So[32*LDP];

    const int tid = threadIdx.x;
    const int wrp = tid >> 5;
    const int t3  = tid & 3;
    const int g   = (tid & 31) >> 2;
    const int m0  = wrp * 16;
    const int h   = blockIdx.x;
    const int b   = blockIdx.y;
    const float* inb = g_out1_nchw + (size_t)b * PL * HW;

    float acc[4][4];
#pragma unroll
    for (int nt = 0; nt < 4; nt++)
#pragma unroll
        for (int i = 0; i < 4; i++) acc[nt][i] = 0.f;

    float s_a[8], s_b[2];
    auto ld = [&](int kc) {
        const int tap = (kc*16) >> 7;
        const int c0  = (kc*16) & 127;
        const int ky  = tap / 3;
        const int kx  = tap - 3*ky;
        const int yy  = h + ky - 1;
        const bool rv = ((unsigned)yy < HH);
#pragma unroll
        for (int u = 0; u < 8; u++) {
            int idx = u*256 + tid;
            int kr = idx >> 7, p = idx & 127;
            int xp = p + kx - 1;
            float v = 0.f;
            if (rv && (unsigned)xp < WW)
                v = inb[(size_t)(c0 + kr)*HW + yy*WW + xp];
            s_a[u] = v;
        }
#pragma unroll
        for (int u = 0; u < 2; u++) {
            int idx = u*256 + tid;
            int kr = idx >> 5, o = idx & 31;
            s_b[u] = g_wOffP[(size_t)(kc*16 + kr)*32 + o];
        }
    };
    auto sts = [&](int bf) {
#pragma unroll
        for (int u = 0; u < 8; u++) {
            int idx = u*256 + tid;
            int kr = idx >> 7, p = idx & 127;
            Ao[bf][kr*LDP + p] = __uint_as_float(f2tf(s_a[u]));
        }
#pragma unroll
        for (int u = 0; u < 2; u++) {
            int idx = u*256 + tid;
            int kr = idx >> 5, o = idx & 31;
            Bo[bf][kr*OLDB + o] = s_b[u];
        }
    };

    ld(0); sts(0);
    __syncthreads();

    for (int kc = 0; kc < 72; kc++) {
        if (kc < 71) ld(kc + 1);
        const uint32_t* As = (const uint32_t*)Ao[kc & 1];
        const uint32_t* Bs = (const uint32_t*)Bo[kc & 1];
#pragma unroll
        for (int ks = 0; ks < 16; ks += 8) {
            uint32_t a[4];
            a[0] = As[(ks + t3)*LDP + m0 + g];
            a[1] = As[(ks + t3)*LDP + m0 + g + 8];
            a[2] = As[(ks + t3 + 4)*LDP + m0 + g];
            a[3] = As[(ks + t3 + 4)*LDP + m0 + g + 8];
#pragma unroll
            for (int nt = 0; nt < 4; nt++) {
                uint32_t bb[2];
                bb[0] = Bs[(ks + t3)*OLDB + nt*8 + g];
                bb[1] = Bs[(ks + t3 + 4)*OLDB + nt*8 + g];
                mma_tf32(acc[nt], a, bb);
            }
        }
        if (kc < 71) sts((kc + 1) & 1);
        __syncthreads();
    }

#pragma unroll
    for (int nt = 0; nt < 4; nt++) {
        int c0 = nt*8 + 2*t3;
        int plo = m0 + g;
        So[c0*LDP + plo]           = acc[nt][0];
        So[(c0 + 1)*LDP + plo]     = acc[nt][1];
        So[c0*LDP + plo + 8]       = acc[nt][2];
        So[(c0 + 1)*LDP + plo + 8] = acc[nt][3];
    }
    __syncthreads();

    const int p = tid & 127;
    const int half = tid >> 7;
    for (int k = half; k < 9; k += 2) {
        float dy = So[k*LDP + p]        + __ldg(b_off + k);
        float dx = So[(9 + k)*LDP + p]  + __ldg(b_off + 9 + k);
        float z  = So[(18 + k)*LDP + p] + __ldg(b_off + 18 + k);
        float mk = 1.f / (1.f + expf(-z));
        int idx = (b*KK + k)*HW + h*WW + p;
        g_py[idx] = (float)(h - 1 + k/3) + dy;
        g_px[idx] = (float)(p - 1 + k%3) + dx;
        g_mk[idx] = mk;
    }
}

// ---------------- K3: deform GEMM via tf32 mma (pipelined, precomputed corners) ----------------
// SMEM floats: A[2][2176] @0, B[2][2176] @4352, cE[1152*8] @8704 (end 17920)
//              Vs [128*136] @0 ; B2 [16*136] @17408  (after mainloop)   19584 total
#define SMF_A   0
#define SMF_B   4352
#define SMF_CE  8704
#define SMF_V   0
#define SMF_B2  17408
#define SMEM_TOT (19584 * 4)

__global__ __launch_bounds__(256, 2) void k_dgemm(
    const float* __restrict__ b_dc, const float* __restrict__ s2, const float* __restrict__ t2,
    const float* __restrict__ s3a, const float* __restrict__ t3a,
    const float* __restrict__ s3b, const float* __restrict__ t3b,
    float* __restrict__ out)
{
    extern __shared__ __align__(16) float smf[];
    float* cE = smf + SMF_CE;

    const int tid  = threadIdx.x;
    const int wrp  = tid >> 5;
    const int t3   = tid & 3;
    const int g    = (tid & 31) >> 2;
    const int m0   = (wrp & 3) * 32;
    const int n0   = (wrp >> 2) * 64;
    const int gpos = tid >> 1;
    const int cg   = (tid & 1) * 8;
    const int bkk  = (tid*2) >> 5;
    const int bo4  = ((tid*2) & 31) * 4;
    const int pos0 = blockIdx.x * 128;
    const int b    = pos0 >> 14;
    const int pim0 = pos0 & (HW - 1);

    // precompute bilinear corner constants: cE[ci*8] = {w00,w01,w10,w11, i00,i01,i10,i11}
    for (int idx = tid; idx < 1152; idx += 256) {
        int k = idx >> 7, p = idx & 127;
        int gidx = (b*KK + k)*HW + pim0 + p;
        float py = g_py[gidx], px = g_px[gidx], mk = g_mk[gidx];
        float fy = floorf(py), fx = floorf(px);
        float wy = py - fy, wx = px - fx;
        int y0 = (int)fy, x0 = (int)fx;
        bool y0k = ((unsigned)y0 < HH), y1k = ((unsigned)(y0+1) < HH);
        bool x0k = ((unsigned)x0 < WW), x1k = ((unsigned)(x0+1) < WW);
        float w00 = (y0k && x0k) ? (1.f-wy)*(1.f-wx)*mk : 0.f;
        float w01 = (y0k && x1k) ? (1.f-wy)*wx*mk       : 0.f;
        float w10 = (y1k && x0k) ? wy*(1.f-wx)*mk       : 0.f;
        float w11 = (y1k && x1k) ? wy*wx*mk             : 0.f;
        int iy0 = min(max(y0, 0), HH-1),     ix0 = min(max(x0, 0), WW-1);
        int iy1 = min(max(y0 + 1, 0), HH-1), ix1 = min(max(x0 + 1, 0), WW-1);
        float* e = cE + idx*8;
        e[0] = w00; e[1] = w01; e[2] = w10; e[3] = w11;
        ((int*)e)[4] = (iy0*WW + ix0)*PL;
        ((int*)e)[5] = (iy0*WW + ix1)*PL;
        ((int*)e)[6] = (iy1*WW + ix0)*PL;
        ((int*)e)[7] = (iy1*WW + ix1)*PL;
    }
    __syncthreads();

    const float* nhwc = g_out1_nhwc + (size_t)b * HW * PL;

    float acc[2][8][4];
#pragma unroll
    for (int mt = 0; mt < 2; mt++)
#pragma unroll
        for (int nt = 0; nt < 8; nt++)
#pragma unroll
            for (int i = 0; i < 4; i++) acc[mt][nt][i] = 0.f;

    float4 q[8];       // staged corner data (4 corners x 8 channels)
    float4 bw0, bw1;   // staged weight tile

    auto ld = [&](int kc) {
        int ci = (kc >> 3)*128 + gpos;
        const int4 iv = *(const int4*)(cE + ci*8 + 4);
        const float* base = nhwc + ((kc & 7) << 4) + cg;
        q[0] = *(const float4*)(base + iv.x);
        q[1] = *(const float4*)(base + iv.x + 4);
        q[2] = *(const float4*)(base + iv.y);
        q[3] = *(const float4*)(base + iv.y + 4);
        q[4] = *(const float4*)(base + iv.z);
        q[5] = *(const float4*)(base + iv.z + 4);
        q[6] = *(const float4*)(base + iv.w);
        q[7] = *(const float4*)(base + iv.w + 4);
        const float* src = g_wDcB + ((size_t)kc*16 + bkk)*PL + bo4;
        bw0 = *(const float4*)src;
        bw1 = *(const float4*)(src + 4);
    };
    auto sts = [&](int kc, int bf) {
        int ci = (kc >> 3)*128 + gpos;
        const float4 wv = *(const float4*)(cE + ci*8);
        float* Ab = smf + SMF_A + bf * 2176;
        float* Bb = smf + SMF_B + bf * 2176;
        float st[8];
        st[0] = q[0].x*wv.x + q[2].x*wv.y + q[4].x*wv.z + q[6].x*wv.w;
        st[1] = q[0].y*wv.x + q[2].y*wv.y + q[4].y*wv.z + q[6].y*wv.w;
        st[2] = q[0].z*wv.x + q[2].z*wv.y + q[4].z*wv.z + q[6].z*wv.w;
        st[3] = q[0].w*wv.x + q[2].w*wv.y + q[4].w*wv.z + q[6].w*wv.w;
        st[4] = q[1].x*wv.x + q[3].x*wv.y + q[5].x*wv.z + q[7].x*wv.w;
        st[5] = q[1].y*wv.x + q[3].y*wv.y + q[5].y*wv.z + q[7].y*wv.w;
        st[6] = q[1].z*wv.x + q[3].z*wv.y + q[5].z*wv.z + q[7].z*wv.w;
        st[7] = q[1].w*wv.x + q[3].w*wv.y + q[5].w*wv.z + q[7].w*wv.w;
#pragma unroll
        for (int j = 0; j < 8; j++)
            Ab[(cg + j)*LDP + gpos] = __uint_as_float(f2tf(st[j]));
        *(float4*)&Bb[bkk*LDP + bo4]     = bw0;
        *(float4*)&Bb[bkk*LDP + bo4 + 4] = bw1;
    };

    ld(0); sts(0, 0);
    __syncthreads();

    for (int kc = 0; kc < 72; kc++) {
        if (kc < 71) ld(kc + 1);
        const uint32_t* As = (const uint32_t*)(smf + SMF_A + (kc & 1) * 2176);
        const uint32_t* Bs = (const uint32_t*)(smf + SMF_B + (kc & 1) * 2176);
#pragma unroll
        for (int ks = 0; ks < 16; ks += 8) {
            uint32_t a[2][4];
#pragma unroll
            for (int mt = 0; mt < 2; mt++) {
                int rb = m0 + mt*16 + g;
                a[mt][0] = As[(ks + t3)*LDP + rb];
                a[mt][1] = As[(ks + t3)*LDP + rb + 8];
                a[mt][2] = As[(ks + t3 + 4)*LDP + rb];
                a[mt][3] = As[(ks + t3 + 4)*LDP + rb + 8];
            }
#pragma unroll
            for (int nt = 0; nt < 8; nt++) {
                uint32_t bb[2];
                bb[0] = Bs[(ks + t3)*LDP + n0 + nt*8 + g];
                bb[1] = Bs[(ks + t3 + 4)*LDP + n0 + nt*8 + g];
                mma_tf32(acc[0][nt], a[0], bb);
                mma_tf32(acc[1][nt], a[1], bb);
            }
        }
        if (kc < 71) sts(kc + 1, (kc + 1) & 1);
        __syncthreads();
    }

    // epilogue 1: v = relu(bn2(acc + b_dc)) -> Vs[c][pos] (tf32 bits)
    float* Vs = smf + SMF_V;
#pragma unroll
    for (int nt = 0; nt < 8; nt++) {
        int c0 = n0 + nt*8 + 2*t3;
        float b0 = __ldg(b_dc + c0),     ss0 = __ldg(s2 + c0),     tt0 = __ldg(t2 + c0);
        float b1 = __ldg(b_dc + c0 + 1), ss1 = __ldg(s2 + c0 + 1), tt1 = __ldg(t2 + c0 + 1);
#pragma unroll
        for (int mt = 0; mt < 2; mt++) {
            int plo = m0 + mt*16 + g;
            float v0 = fmaxf((acc[mt][nt][0] + b0) * ss0 + tt0, 0.f);
            float v1 = fmaxf((acc[mt][nt][1] + b1) * ss1 + tt1, 0.f);
            float v2 = fmaxf((acc[mt][nt][2] + b0) * ss0 + tt0, 0.f);
            float v3 = fmaxf((acc[mt][nt][3] + b1) * ss1 + tt1, 0.f);
            Vs[c0*LDP + plo]           = __uint_as_float(f2tf(v0));
            Vs[(c0 + 1)*LDP + plo]     = __uint_as_float(f2tf(v1));
            Vs[c0*LDP + plo + 8]       = __uint_as_float(f2tf(v2));
            Vs[(c0 + 1)*LDP + plo + 8] = __uint_as_float(f2tf(v3));
        }
    }
    __syncthreads();

    // GEMM2: conv3, K=128 in 8 chunks of 16
    float acc3[2][8][4];
#pragma unroll
    for (int mt = 0; mt < 2; mt++)
#pragma unroll
        for (int nt = 0; nt < 8; nt++)
#pragma unroll
            for (int i = 0; i < 4; i++) acc3[mt][nt][i] = 0.f;

    float* B2 = smf + SMF_B2;
    for (int cb = 0; cb < 8; cb++) {
        float4 r[2];
#pragma unroll
        for (int u = 0; u < 2; u++) {
            int qd = u*256 + tid, rr = qd >> 5, col4 = (qd & 31) * 4;
            r[u] = *(const float4*)&g_w3T[((size_t)cb*16 + rr)*PL + col4];
        }
        __syncthreads();
#pragma unroll
        for (int u = 0; u < 2; u++) {
            int qd = u*256 + tid, rr = qd >> 5, col4 = (qd & 31) * 4;
            *(float4*)&B2[rr*LDP + col4] = r[u];
        }
        __syncthreads();
        const uint32_t* As = (const uint32_t*)Vs;
        const uint32_t* Bs = (const uint32_t*)B2;
#pragma unroll
        for (int ks = 0; ks < 16; ks += 8) {
            uint32_t a[2][4];
#pragma unroll
            for (int mt = 0; mt < 2; mt++) {
                int rb = m0 + mt*16 + g;
                a[mt][0] = As[(cb*16 + ks + t3)*LDP + rb];
                a[mt][1] = As[(cb*16 + ks + t3)*LDP + rb + 8];
                a[mt][2] = As[(cb*16 + ks + t3 + 4)*LDP + rb];
                a[mt][3] = As[(cb*16 + ks + t3 + 4)*LDP + rb + 8];
            }
#pragma unroll
            for (int nt = 0; nt < 8; nt++) {
                uint32_t bb[2];
                bb[0] = Bs[(ks + t3)*LDP + n0 + nt*8 + g];
                bb[1] = Bs[(ks + t3 + 4)*LDP + n0 + nt*8 + g];
                mma_tf32(acc3[0][nt], a[0], bb);
                mma_tf32(acc3[1][nt], a[1], bb);
            }
        }
    }
    __syncthreads();

    // epilogue 2: bn3a/relu/bn3b -> Fs, then +identity coalesced store
    float* Fs = smf + SMF_V;
#pragma unroll
    for (int nt = 0; nt < 8; nt++) {
        int c0 = n0 + nt*8 + 2*t3;
        float sa0 = __ldg(s3a + c0),     ta0 = __ldg(t3a + c0);
        float sb0 = __ldg(s3b + c0),     tb0 = __ldg(t3b + c0);
        float sa1 = __ldg(s3a + c0 + 1), ta1 = __ldg(t3a + c0 + 1);
        float sb1 = __ldg(s3b + c0 + 1), tb1 = __ldg(t3b + c0 + 1);
#pragma unroll
        for (int mt = 0; mt < 2; mt++) {
            int plo = m0 + mt*16 + g;
            Fs[c0*LDP + plo]           = fmaxf(acc3[mt][nt][0] * sa0 + ta0, 0.f) * sb0 + tb0;
            Fs[(c0 + 1)*LDP + plo]     = fmaxf(acc3[mt][nt][1] * sa1 + ta1, 0.f) * sb1 + tb1;
            Fs[c0*LDP + plo + 8]       = fmaxf(acc3[mt][nt][2] * sa0 + ta0, 0.f) * sb0 + tb0;
            Fs[(c0 + 1)*LDP + plo + 8] = fmaxf(acc3[mt][nt][3] * sa1 + ta1, 0.f) * sb1 + tb1;
        }
    }
    __syncthreads();

    {
        const int o2 = tid & 127;
        const int ph = tid >> 7;
        size_t base = ((size_t)(b*PL + o2))*HW + pim0 + ph*64;
        const float* frow = Fs + o2*LDP + ph*64;
#pragma unroll
        for (int i = 0; i < 16; i++) {
            float4 f = *(const float4*)&frow[i*4];
            float4 id = *(const float4*)&g_ident[base + i*4];
            *(float4*)&out[base + i*4] = make_float4(
                fmaxf(f.x + id.x, 0.f), fmaxf(f.y + id.y, 0.f),
                fmaxf(f.z + id.z, 0.f), fmaxf(f.w + id.w, 0.f));
        }
    }
}

// ---------------- host ----------------
extern "C" void kernel_launch(void* const* d_in, const int* in_sizes, int n_in,
                              void* d_out, int out_size) {
    const float* x    = (const float*)d_in[0];
    const float* w1   = (const float*)d_in[1];
    const float* s1a  = (const float*)d_in[2];
    const float* t1a  = (const float*)d_in[3];
    const float* s1b  = (const float*)d_in[4];
    const float* t1b  = (const float*)d_in[5];
    const float* w_off= (const float*)d_in[6];
    const float* b_off= (const float*)d_in[7];
    const float* w_dc = (const float*)d_in[8];
    const float* b_dc = (const float*)d_in[9];
    const float* s2   = (const float*)d_in[10];
    const float* t2   = (const float*)d_in[11];
    const float* w3   = (const float*)d_in[12];
    const float* s3a  = (const float*)d_in[13];
    const float* t3a  = (const float*)d_in[14];
    const float* s3b  = (const float*)d_in[15];
    const float* t3b  = (const float*)d_in[16];
    const float* w_ds = (const float*)d_in[17];
    const float* b_ds = (const float*)d_in[18];
    const float* sd   = (const float*)d_in[19];
    const float* td   = (const float*)d_in[20];
    float* out = (float*)d_out;

    k_prep<<<(CK*PL + 255)/256, 256>>>(w_off, w_dc, w3, w1, w_ds);

    cudaFuncSetAttribute(k_cgemm, cudaFuncAttributeMaxDynamicSharedMemorySize, SMEM_TOT_C);
    dim3 g1(HW/128, 2, NB);
    k_cgemm<<<g1, 256, SMEM_TOT_C>>>(x, s1a, t1a, s1b, t1b, b_ds, sd, td);

    dim3 g2(HH, NB);
    k_offset<<<g2, 256>>>(b_off);

    cudaFuncSetAttribute(k_dgemm, cudaFuncAttributeMaxDynamicSharedMemorySize, SMEM_TOT);
    k_dgemm<<<NB*HW/128, 256, SMEM_TOT>>>(b_dc, s2, t2, s3a, t3a, s3b, t3b, out);
}

// round 8
// speedup vs baseline: 3.4745x; 1.2404x over previous
#include <cuda_runtime.h>
#include <cstdint>
#include <math.h>

#define NB  4
#define CIN 256
#define PL  128
#define HH  128
#define WW  128
#define HW  16384
#define KK  9
#define CK  1152   // PL*KK
#define LDP 136
#define LDK 36

// ---- scratch (device globals: allocation-free) ----
__device__ float g_out1_nchw[NB*PL*HW];
__device__ float g_out1_nhwc[NB*HW*PL];
__device__ float g_ident[NB*PL*HW];
__device__ float g_py[NB*KK*HW];
__device__ float g_px[NB*KK*HW];
__device__ float g_mk[NB*KK*HW];
__device__ float g_wOffP[CK*32];          // [tap*128+c][o<27 pad 32] (tf32 bits)
__device__ float g_wDcB[CK*PL];           // [K'=k*128+c][o]          (tf32 bits)
__device__ float g_w3T[PL*PL];            // [c][o]                   (tf32 bits)
__device__ float g_w1T[CIN*PL];           // [c][o]                   (tf32 bits)
__device__ float g_wdsT[CIN*PL];          // [c][o]                   (tf32 bits)

// ---- tf32 mma helpers ----
__device__ __forceinline__ uint32_t f2tf(float x) {
    uint32_t r; asm("cvt.rna.tf32.f32 %0, %1;" : "=r"(r) : "f"(x)); return r;
}
__device__ __forceinline__ void mma_tf32(float d[4], const uint32_t a[4], const uint32_t b[2]) {
    asm volatile("mma.sync.aligned.m16n8k8.row.col.f32.tf32.tf32.f32 "
        "{%0,%1,%2,%3}, {%4,%5,%6,%7}, {%8,%9}, {%0,%1,%2,%3};"
        : "+f"(d[0]), "+f"(d[1]), "+f"(d[2]), "+f"(d[3])
        : "r"(a[0]), "r"(a[1]), "r"(a[2]), "r"(a[3]), "r"(b[0]), "r"(b[1]));
}

// ---------------- K0: weight transposes + tf32 conversion ----------------
__global__ void k_prep(const float* __restrict__ w_off,
                       const float* __restrict__ w_dc,
                       const float* __restrict__ w3,
                       const float* __restrict__ w1,
                       const float* __restrict__ wds) {
    int i = blockIdx.x * blockDim.x + threadIdx.x;
    if (i < CK*32) {
        int row = i >> 5, o = i & 31;
        int tap = row >> 7, c = row & 127;
        g_wOffP[i] = (o < 27) ? __uint_as_float(f2tf(w_off[o*CK + c*KK + tap])) : 0.f;
    }
    if (i < CK*PL) {
        int o = i & 127, t = i >> 7;
        int c = t & 127, k = t >> 7;
        g_wDcB[i] = __uint_as_float(f2tf(w_dc[(o*PL + c)*KK + k]));
    }
    if (i < CIN*PL) {
        int c = i >> 7, o = i & 127;
        g_w1T[i]  = __uint_as_float(f2tf(w1[o*CIN + c]));
        g_wdsT[i] = __uint_as_float(f2tf(wds[o*CIN + c]));
    }
    if (i < PL*PL) {
        int c = i >> 7, o = i & 127;
        g_w3T[i] = __uint_as_float(f2tf(w3[o*PL + c]));
    }
}

// ---------------- K1: conv1 / downsample via tf32 mma (pipelined) ----------------
#define SMEM_TOT_C (17408 * 4)
__global__ __launch_bounds__(256, 2) void k_cgemm(
    const float* __restrict__ x,
    const float* __restrict__ s1a, const float* __restrict__ t1a,
    const float* __restrict__ s1b, const float* __restrict__ t1b,
    const float* __restrict__ bds, const float* __restrict__ sd, const float* __restrict__ td)
{
    extern __shared__ __align__(16) float smf[];

    const int tid  = threadIdx.x;
    const int wrp  = tid >> 5;
    const int t3   = tid & 3;
    const int g    = (tid & 31) >> 2;
    const int m0   = (wrp & 3) * 32;
    const int n0   = (wrp >> 2) * 64;
    const int pos0 = blockIdx.x * 128;
    const int job  = blockIdx.y;
    const int b    = blockIdx.z;
    const float* wT = job ? g_wdsT : g_w1T;
    const float* xb = x + (size_t)b * CIN * HW + pos0;

    float acc[2][8][4];
#pragma unroll
    for (int mt = 0; mt < 2; mt++)
#pragma unroll
        for (int nt = 0; nt < 8; nt++)
#pragma unroll
            for (int i = 0; i < 4; i++) acc[mt][nt][i] = 0.f;

    float4 sa[2], sb[2];
    const int lrow = tid >> 5;
    const int lc4a = (tid & 31) * 4;
    auto ld = [&](int kc) {
#pragma unroll
        for (int u = 0; u < 2; u++) {
            int row = lrow + u*8;
            sa[u] = *(const float4*)&xb[(size_t)(kc*16 + row) * HW + lc4a];
            sb[u] = *(const float4*)&wT[(kc*16 + row)*PL + lc4a];
        }
    };
    auto sts = [&](int bf) {
        float* Ab = smf + bf * 2176;
        float* Bb = smf + 4352 + bf * 2176;
#pragma unroll
        for (int u = 0; u < 2; u++) {
            int row = lrow + u*8;
            uint4 tv = make_uint4(f2tf(sa[u].x), f2tf(sa[u].y), f2tf(sa[u].z), f2tf(sa[u].w));
            *(uint4*)&Ab[row*LDP + lc4a] = tv;
            *(float4*)&Bb[row*LDP + lc4a] = sb[u];
        }
    };

    ld(0); sts(0);
    __syncthreads();

    for (int kc = 0; kc < 16; kc++) {
        if (kc < 15) ld(kc + 1);
        const uint32_t* As = (const uint32_t*)(smf + (kc & 1) * 2176);
        const uint32_t* Bs = (const uint32_t*)(smf + 4352 + (kc & 1) * 2176);
#pragma unroll
        for (int ks = 0; ks < 16; ks += 8) {
            uint32_t a[2][4];
#pragma unroll
            for (int mt = 0; mt < 2; mt++) {
                int rb = m0 + mt*16 + g;
                a[mt][0] = As[(ks + t3)*LDP + rb];
                a[mt][1] = As[(ks + t3)*LDP + rb + 8];
                a[mt][2] = As[(ks + t3 + 4)*LDP + rb];
                a[mt][3] = As[(ks + t3 + 4)*LDP + rb + 8];
            }
#pragma unroll
            for (int nt = 0; nt < 8; nt++) {
                uint32_t bb[2];
                bb[0] = Bs[(ks + t3)*LDP + n0 + nt*8 + g];
                bb[1] = Bs[(ks + t3 + 4)*LDP + n0 + nt*8 + g];
                mma_tf32(acc[0][nt], a[0], bb);
                mma_tf32(acc[1][nt], a[1], bb);
            }
        }
        if (kc < 15) sts((kc + 1) & 1);
        __syncthreads();
    }

    float* Fs = smf;
#pragma unroll
    for (int nt = 0; nt < 8; nt++) {
        int c0 = n0 + nt*8 + 2*t3;
        float p0a, p0b, p0c, p0d, p1a, p1b, p1c, p1d;
        if (job == 0) {
            p0a = __ldg(s1a + c0);     p0b = __ldg(t1a + c0);
            p0c = __ldg(s1b + c0);     p0d = __ldg(t1b + c0);
            p1a = __ldg(s1a + c0 + 1); p1b = __ldg(t1a + c0 + 1);
            p1c = __ldg(s1b + c0 + 1); p1d = __ldg(t1b + c0 + 1);
        } else {
            p0a = __ldg(bds + c0);     p0b = __ldg(sd + c0);     p0c = __ldg(td + c0);
            p1a = __ldg(bds + c0 + 1); p1b = __ldg(sd + c0 + 1); p1c = __ldg(td + c0 + 1);
            p0d = p1d = 0.f;
        }
#pragma unroll
        for (int mt = 0; mt < 2; mt++) {
            int plo = m0 + mt*16 + g;
            float v0 = acc[mt][nt][0], v1 = acc[mt][nt][1];
            float v2 = acc[mt][nt][2], v3 = acc[mt][nt][3];
            if (job == 0) {
                v0 = fmaxf(fmaxf(v0 * p0a + p0b, 0.f) * p0c + p0d, 0.f);
                v2 = fmaxf(fmaxf(v2 * p0a + p0b, 0.f) * p0c + p0d, 0.f);
                v1 = fmaxf(fmaxf(v1 * p1a + p1b, 0.f) * p1c + p1d, 0.f);
                v3 = fmaxf(fmaxf(v3 * p1a + p1b, 0.f) * p1c + p1d, 0.f);
            } else {
                v0 = (v0 + p0a) * p0b + p0c;  v2 = (v2 + p0a) * p0b + p0c;
                v1 = (v1 + p1a) * p1b + p1c;  v3 = (v3 + p1a) * p1b + p1c;
            }
            Fs[c0*LDP + plo]           = v0;
            Fs[(c0 + 1)*LDP + plo]     = v1;
            Fs[c0*LDP + plo + 8]       = v2;
            Fs[(c0 + 1)*LDP + plo + 8] = v3;
        }
    }
    __syncthreads();

    const int o2 = tid & 127;
    const int ph = tid >> 7;
    float* dstN = (job == 0) ? g_out1_nchw : g_ident;
    {
        size_t base = ((size_t)(b*PL + o2))*HW + pos0 + ph*64;
        const float* frow = Fs + o2*LDP + ph*64;
#pragma unroll
        for (int i = 0; i < 16; i++)
            *(float4*)&dstN[base + i*4] = *(const float4*)&frow[i*4];
    }
    if (job == 0) {
        size_t base = ((size_t)(b*HW + pos0 + o2))*PL + ph*64;
#pragma unroll
        for (int i = 0; i < 16; i++) {
            int c = ph*64 + i*4;
            float4 v = make_float4(Fs[c*LDP + o2], Fs[(c+1)*LDP + o2],
                                   Fs[(c+2)*LDP + o2], Fs[(c+3)*LDP + o2]);
            *(float4*)&g_out1_nhwc[base + i*4] = v;
        }
    }
}

// ---------------- K2: offset/mask 3x3 conv via tf32 mma (pipelined) ----------------
#define OLDB 40
__global__ __launch_bounds__(256) void k_offset(const float* __restrict__ b_off) {
    __shared__ __align__(16) float Ao[2][16*LDP];
    __shared__ __align__(16) float Bo[2][16*OLDB];
    __shared__ __align__(16) float So[32*LDP];

    const int tid = threadIdx.x;
    const int wrp = tid >> 5;
    const int t3  = tid & 3;
    const int g   = (tid & 31) >> 2;
    const int m0  = wrp * 16;
    const int h   = blockIdx.x;
    const int b   = blockIdx.y;
    const float* inb = g_out1_nchw + (size_t)b * PL * HW;

    float acc[4][4];
#pragma unroll
    for (int nt = 0; nt < 4; nt++)
#pragma unroll
        for (int i = 0; i < 4; i++) acc[nt][i] = 0.f;

    float s_a[8], s_b[2];
    auto ld = [&](int kc) {
        const int tap = (kc*16) >> 7;
        const int c0  = (kc*16) & 127;
        const int ky  = tap / 3;
        const int kx  = tap - 3*ky;
        const int yy  = h + ky - 1;
        const bool rv = ((unsigned)yy < HH);
#pragma unroll
        for (int u = 0; u < 8; u++) {
            int idx = u*256 + tid;
            int kr = idx >> 7, p = idx & 127;
            int xp = p + kx - 1;
            float v = 0.f;
            if (rv && (unsigned)xp < WW)
                v = inb[(size_t)(c0 + kr)*HW + yy*WW + xp];
            s_a[u] = v;
        }
#pragma unroll
        for (int u = 0; u < 2; u++) {
            int idx = u*256 + tid;
            int kr = idx >> 5, o = idx & 31;
            s_b[u] = g_wOffP[(size_t)(kc*16 + kr)*32 + o];
        }
    };
    auto sts = [&](int bf) {
#pragma unroll
        for (int u = 0; u < 8; u++) {
            int idx = u*256 + tid;
            int kr = idx >> 7, p = idx & 127;
            Ao[bf][kr*LDP + p] = __uint_as_float(f2tf(s_a[u]));
        }
#pragma unroll
        for (int u = 0; u < 2; u++) {
            int idx = u*256 + tid;
            int kr = idx >> 5, o = idx & 31;
            Bo[bf][kr*OLDB + o] = s_b[u];
        }
    };

    ld(0); sts(0);
    __syncthreads();

    for (int kc = 0; kc < 72; kc++) {
        if (kc < 71) ld(kc + 1);
        const uint32_t* As = (const uint32_t*)Ao[kc & 1];
        const uint32_t* Bs = (const uint32_t*)Bo[kc & 1];
#pragma unroll
        for (int ks = 0; ks < 16; ks += 8) {
            uint32_t a[4];
            a[0] = As[(ks + t3)*LDP + m0 + g];
            a[1] = As[(ks + t3)*LDP + m0 + g + 8];
            a[2] = As[(ks + t3 + 4)*LDP + m0 + g];
            a[3] = As[(ks + t3 + 4)*LDP + m0 + g + 8];
#pragma unroll
            for (int nt = 0; nt < 4; nt++) {
                uint32_t bb[2];
                bb[0] = Bs[(ks + t3)*OLDB + nt*8 + g];
                bb[1] = Bs[(ks + t3 + 4)*OLDB + nt*8 + g];
                mma_tf32(acc[nt], a, bb);
            }
        }
        if (kc < 71) sts((kc + 1) & 1);
        __syncthreads();
    }

#pragma unroll
    for (int nt = 0; nt < 4; nt++) {
        int c0 = nt*8 + 2*t3;
        int plo = m0 + g;
        So[c0*LDP + plo]           = acc[nt][0];
        So[(c0 + 1)*LDP + plo]     = acc[nt][1];
        So[c0*LDP + plo + 8]       = acc[nt][2];
        So[(c0 + 1)*LDP + plo + 8] = acc[nt][3];
    }
    __syncthreads();

    const int p = tid & 127;
    const int half = tid >> 7;
    for (int k = half; k < 9; k += 2) {
        float dy = So[k*LDP + p]        + __ldg(b_off + k);
        float dx = So[(9 + k)*LDP + p]  + __ldg(b_off + 9 + k);
        float z  = So[(18 + k)*LDP + p] + __ldg(b_off + 18 + k);
        float mk = 1.f / (1.f + expf(-z));
        int idx = (b*KK + k)*HW + h*WW + p;
        g_py[idx] = (float)(h - 1 + k/3) + dy;
        g_px[idx] = (float)(p - 1 + k%3) + dx;
        g_mk[idx] = mk;
    }
}

// ---------------- K3: deform GEMM, dense channel-major gather ----------------
// SMEM floats: A [128][36] @0 (4608), B [32][136] @4608 (4352), cE @8960 (9216) -> 18176
//              Vs [128*136] @0 (17408) ; B2 [16*136] @17408 (2176) -> 19584 total
#define SMF_A   0
#define SMF_B   4608
#define SMF_CE  8960
#define SMF_V   0
#define SMF_B2  17408
#define SMEM_TOT (19584 * 4)

__global__ __launch_bounds__(256, 2) void k_dgemm(
    const float* __restrict__ b_dc, const float* __restrict__ s2, const float* __restrict__ t2,
    const float* __restrict__ s3a, const float* __restrict__ t3a,
    const float* __restrict__ s3b, const float* __restrict__ t3b,
    float* __restrict__ out)
{
    extern __shared__ __align__(16) float smf[];
    float* cE = smf + SMF_CE;

    const int tid  = threadIdx.x;
    const int wrp  = tid >> 5;
    const int lane = tid & 31;
    const int t3   = tid & 3;
    const int g    = (tid & 31) >> 2;
    const int m0   = (wrp & 3) * 32;
    const int n0   = (wrp >> 2) * 64;
    const int sp   = lane >> 3;      // subpos 0..3
    const int cq   = lane & 7;       // channel quad 0..7
    const int pos0 = blockIdx.x * 128;
    const int b    = pos0 >> 14;
    const int pim0 = pos0 & (HW - 1);

    // precompute bilinear constants: cE[ci*8] = {w00,w01,w10,w11, i00,i01,i10,i11}
    for (int idx = tid; idx < 1152; idx += 256) {
        int k = idx >> 7, p = idx & 127;
        int gidx = (b*KK + k)*HW + pim0 + p;
        float py = g_py[gidx], px = g_px[gidx], mk = g_mk[gidx];
        float fy = floorf(py), fx = floorf(px);
        float wy = py - fy, wx = px - fx;
        int y0 = (int)fy, x0 = (int)fx;
        bool y0k = ((unsigned)y0 < HH), y1k = ((unsigned)(y0+1) < HH);
        bool x0k = ((unsigned)x0 < WW), x1k = ((unsigned)(x0+1) < WW);
        float w00 = (y0k && x0k) ? (1.f-wy)*(1.f-wx)*mk : 0.f;
        float w01 = (y0k && x1k) ? (1.f-wy)*wx*mk       : 0.f;
        float w10 = (y1k && x0k) ? wy*(1.f-wx)*mk       : 0.f;
        float w11 = (y1k && x1k) ? wy*wx*mk             : 0.f;
        int iy0 = min(max(y0, 0), HH-1),     ix0 = min(max(x0, 0), WW-1);
        int iy1 = min(max(y0 + 1, 0), HH-1), ix1 = min(max(x0 + 1, 0), WW-1);
        float* e = cE + idx*8;
        e[0] = w00; e[1] = w01; e[2] = w10; e[3] = w11;
        ((int*)e)[4] = (iy0*WW + ix0)*PL;
        ((int*)e)[5] = (iy0*WW + ix1)*PL;
        ((int*)e)[6] = (iy1*WW + ix0)*PL;
        ((int*)e)[7] = (iy1*WW + ix1)*PL;
    }
    __syncthreads();

    const float* nhwc = g_out1_nhwc + (size_t)b * HW * PL;
    float* Ab = smf + SMF_A;
    float* Bb = smf + SMF_B;

    float acc[2][8][4];
#pragma unroll
    for (int mt = 0; mt < 2; mt++)
#pragma unroll
        for (int nt = 0; nt < 8; nt++)
#pragma unroll
            for (int i = 0; i < 4; i++) acc[mt][nt][i] = 0.f;

    for (int kc = 0; kc < 36; kc++) {
        const int tap = kc >> 2;
        const int c0  = (kc & 3) * 32;
        // fill A: dense channel-major gather. warp-instr = 4 positions x 128B line.
#pragma unroll
        for (int it = 0; it < 4; it++) {
            int p  = wrp*16 + it*4 + sp;
            int ci = tap*128 + p;
            const float4 wv = *(const float4*)(cE + ci*8);
            const int4  iv  = *(const int4*)(cE + ci*8 + 4);
            const float* base = nhwc + c0 + cq*4;
            float4 q0 = *(const float4*)(base + iv.x);
            float4 q1 = *(const float4*)(base + iv.y);
            float4 q2 = *(const float4*)(base + iv.z);
            float4 q3 = *(const float4*)(base + iv.w);
            float ox = q0.x*wv.x + q1.x*wv.y + q2.x*wv.z + q3.x*wv.w;
            float oy = q0.y*wv.x + q1.y*wv.y + q2.y*wv.z + q3.y*wv.w;
            float oz = q0.z*wv.x + q1.z*wv.y + q2.z*wv.z + q3.z*wv.w;
            float ow = q0.w*wv.x + q1.w*wv.y + q2.w*wv.z + q3.w*wv.w;
            uint4 tv = make_uint4(f2tf(ox), f2tf(oy), f2tf(oz), f2tf(ow));
            *(uint4*)&Ab[p*LDK + cq*4] = tv;
        }
        // fill B: 32 rows x 128 outs
#pragma unroll
        for (int u = 0; u < 4; u++) {
            int q = u*256 + tid, rr = q >> 5, col4 = (q & 31) * 4;
            *(float4*)&Bb[rr*LDP + col4] =
                *(const float4*)&g_wDcB[((size_t)kc*32 + rr)*PL + col4];
        }
        __syncthreads();
        const uint32_t* As = (const uint32_t*)Ab;
        const uint32_t* Bs = (const uint32_t*)Bb;
#pragma unroll
        for (int ks = 0; ks < 32; ks += 8) {
            uint32_t a[2][4];
#pragma unroll
            for (int mt = 0; mt < 2; mt++) {
                int rb = m0 + mt*16 + g;
                a[mt][0] = As[rb*LDK + ks + t3];
                a[mt][1] = As[(rb + 8)*LDK + ks + t3];
                a[mt][2] = As[rb*LDK + ks + t3 + 4];
                a[mt][3] = As[(rb + 8)*LDK + ks + t3 + 4];
            }
#pragma unroll
            for (int nt = 0; nt < 8; nt++) {
                uint32_t bb[2];
                bb[0] = Bs[(ks + t3)*LDP + n0 + nt*8 + g];
                bb[1] = Bs[(ks + t3 + 4)*LDP + n0 + nt*8 + g];
                mma_tf32(acc[0][nt], a[0], bb);
                mma_tf32(acc[1][nt], a[1], bb);
            }
        }
        __syncthreads();
    }

    // epilogue 1: v = relu(bn2(acc + b_dc)) -> Vs[c][pos] (tf32 bits)
    float* Vs = smf + SMF_V;
#pragma unroll
    for (int nt = 0; nt < 8; nt++) {
        int c0 = n0 + nt*8 + 2*t3;
        float b0 = __ldg(b_dc + c0),     ss0 = __ldg(s2 + c0),     tt0 = __ldg(t2 + c0);
        float b1 = __ldg(b_dc + c0 + 1), ss1 = __ldg(s2 + c0 + 1), tt1 = __ldg(t2 + c0 + 1);
#pragma unroll
        for (int mt = 0; mt < 2; mt++) {
            int plo = m0 + mt*16 + g;
            float v0 = fmaxf((acc[mt][nt][0] + b0) * ss0 + tt0, 0.f);
            float v1 = fmaxf((acc[mt][nt][1] + b1) * ss1 + tt1, 0.f);
            float v2 = fmaxf((acc[mt][nt][2] + b0) * ss0 + tt0, 0.f);
            float v3 = fmaxf((acc[mt][nt][3] + b1) * ss1 + tt1, 0.f);
            Vs[c0*LDP + plo]           = __uint_as_float(f2tf(v0));
            Vs[(c0 + 1)*LDP + plo]     = __uint_as_float(f2tf(v1));
            Vs[c0*LDP + plo + 8]       = __uint_as_float(f2tf(v2));
            Vs[(c0 + 1)*LDP + plo + 8] = __uint_as_float(f2tf(v3));
        }
    }
    __syncthreads();

    // GEMM2: conv3, K=128 in 8 chunks of 16
    float acc3[2][8][4];
#pragma unroll
    for (int mt = 0; mt < 2; mt++)
#pragma unroll
        for (int nt = 0; nt < 8; nt++)
#pragma unroll
            for (int i = 0; i < 4; i++) acc3[mt][nt][i] = 0.f;

    float* B2 = smf + SMF_B2;
    for (int cb = 0; cb < 8; cb++) {
        float4 r[2];
#pragma unroll
        for (int u = 0; u < 2; u++) {
            int qd = u*256 + tid, rr = qd >> 5, col4 = (qd & 31) * 4;
            r[u] = *(const float4*)&g_w3T[((size_t)cb*16 + rr)*PL + col4];
        }
        __syncthreads();
#pragma unroll
        for (int u = 0; u < 2; u++) {
            int qd = u*256 + tid, rr = qd >> 5, col4 = (qd & 31) * 4;
            *(float4*)&B2[rr*LDP + col4] = r[u];
        }
        __syncthreads();
        const uint32_t* As = (const uint32_t*)Vs;
        const uint32_t* Bs = (const uint32_t*)B2;
#pragma unroll
        for (int ks = 0; ks < 16; ks += 8) {
            uint32_t a[2][4];
#pragma unroll
            for (int mt = 0; mt < 2; mt++) {
                int rb = m0 + mt*16 + g;
                a[mt][0] = As[(cb*16 + ks + t3)*LDP + rb];
                a[mt][1] = As[(cb*16 + ks + t3)*LDP + rb + 8];
                a[mt][2] = As[(cb*16 + ks + t3 + 4)*LDP + rb];
                a[mt][3] = As[(cb*16 + ks + t3 + 4)*LDP + rb + 8];
            }
#pragma unroll
            for (int nt = 0; nt < 8; nt++) {
                uint32_t bb[2];
                bb[0] = Bs[(ks + t3)*LDP + n0 + nt*8 + g];
                bb[1] = Bs[(ks + t3 + 4)*LDP + n0 + nt*8 + g];
                mma_tf32(acc3[0][nt], a[0], bb);
                mma_tf32(acc3[1][nt], a[1], bb);
            }
        }
    }
    __syncthreads();

    // epilogue 2: bn3a/relu/bn3b -> Fs, then +identity coalesced store
    float* Fs = smf + SMF_V;
#pragma unroll
    for (int nt = 0; nt < 8; nt++) {
        int c0 = n0 + nt*8 + 2*t3;
        float sa0 = __ldg(s3a + c0),     ta0 = __ldg(t3a + c0);
        float sb0 = __ldg(s3b + c0),     tb0 = __ldg(t3b + c0);
        float sa1 = __ldg(s3a + c0 + 1), ta1 = __ldg(t3a + c0 + 1);
        float sb1 = __ldg(s3b + c0 + 1), tb1 = __ldg(t3b + c0 + 1);
#pragma unroll
        for (int mt = 0; mt < 2; mt++) {
            int plo = m0 + mt*16 + g;
            Fs[c0*LDP + plo]           = fmaxf(acc3[mt][nt][0] * sa0 + ta0, 0.f) * sb0 + tb0;
            Fs[(c0 + 1)*LDP + plo]     = fmaxf(acc3[mt][nt][1] * sa1 + ta1, 0.f) * sb1 + tb1;
            Fs[c0*LDP + plo + 8]       = fmaxf(acc3[mt][nt][2] * sa0 + ta0, 0.f) * sb0 + tb0;
            Fs[(c0 + 1)*LDP + plo + 8] = fmaxf(acc3[mt][nt][3] * sa1 + ta1, 0.f) * sb1 + tb1;
        }
    }
    __syncthreads();

    {
        const int o2 = tid & 127;
        const int ph = tid >> 7;
        size_t base = ((size_t)(b*PL + o2))*HW + pim0 + ph*64;
        const float* frow = Fs + o2*LDP + ph*64;
#pragma unroll
        for (int i = 0; i < 16; i++) {
            float4 f = *(const float4*)&frow[i*4];
            float4 id = *(const float4*)&g_ident[base + i*4];
            *(float4*)&out[base + i*4] = make_float4(
                fmaxf(f.x + id.x, 0.f), fmaxf(f.y + id.y, 0.f),
                fmaxf(f.z + id.z, 0.f), fmaxf(f.w + id.w, 0.f));
        }
    }
}

// ---------------- host ----------------
extern "C" void kernel_launch(void* const* d_in, const int* in_sizes, int n_in,
                              void* d_out, int out_size) {
    const float* x    = (const float*)d_in[0];
    const float* w1   = (const float*)d_in[1];
    const float* s1a  = (const float*)d_in[2];
    const float* t1a  = (const float*)d_in[3];
    const float* s1b  = (const float*)d_in[4];
    const float* t1b  = (const float*)d_in[5];
    const float* w_off= (const float*)d_in[6];
    const float* b_off= (const float*)d_in[7];
    const float* w_dc = (const float*)d_in[8];
    const float* b_dc = (const float*)d_in[9];
    const float* s2   = (const float*)d_in[10];
    const float* t2   = (const float*)d_in[11];
    const float* w3   = (const float*)d_in[12];
    const float* s3a  = (const float*)d_in[13];
    const float* t3a  = (const float*)d_in[14];
    const float* s3b  = (const float*)d_in[15];
    const float* t3b  = (const float*)d_in[16];
    const float* w_ds = (const float*)d_in[17];
    const float* b_ds = (const float*)d_in[18];
    const float* sd   = (const float*)d_in[19];
    const float* td   = (const float*)d_in[20];
    float* out = (float*)d_out;

    k_prep<<<(CK*PL + 255)/256, 256>>>(w_off, w_dc, w3, w1, w_ds);

    cudaFuncSetAttribute(k_cgemm, cudaFuncAttributeMaxDynamicSharedMemorySize, SMEM_TOT_C);
    dim3 g1(HW/128, 2, NB);
    k_cgemm<<<g1, 256, SMEM_TOT_C>>>(x, s1a, t1a, s1b, t1b, b_ds, sd, td);

    dim3 g2(HH, NB);
    k_offset<<<g2, 256>>>(b_off);

    cudaFuncSetAttribute(k_dgemm, cudaFuncAttributeMaxDynamicSharedMemorySize, SMEM_TOT);
    k_dgemm<<<NB*HW/128, 256, SMEM_TOT>>>(b_dc, s2, t2, s3a, t3a, s3b, t3b, out);
}